// round 13
// baseline (speedup 1.0000x reference)
#include <cuda_runtime.h>
#include <cuda_fp16.h>
#include <math.h>
#include <stdint.h>

// Problem constants (fixed shapes from reference)
#define BD     2
#define SEQ    4096
#define HID    2048
#define NHEAD  16
#define DH     128
#define BLK    256
#define NB     16          // SEQ/BLK
#define MROWS  8192        // BD*SEQ
#define QKVC   6144        // 3*HID
#define BHN    32          // BD*NHEAD
#define NZ     (BHN * NB)  // 512 (bh, blk) pairs

// ---------------- scratch (static device memory; no allocs allowed) ----------
__device__ float  g_attn[BHN * SEQ * DH];        // attention output (b,h,n,d) fp32
__device__ float  g_gate[MROWS * HID];           // sigmoid(x @ Wg^T)
__device__ float  g_kvblk[NZ * DH * DH];         // per-block KV contributions fp32
__device__ __half g_qh[BHN * SEQ * DH];          // q fp16 (b,h,n,d)
__device__ __half g_kh[BHN * SEQ * DH];
__device__ __half g_vh[BHN * SEQ * DH];
__device__ __half g_qs[BHN * SEQ * DH];          // q * q_decay fp16
__device__ __half g_kt[NZ * DH * BLK];           // k_decay*k transposed [z][d][t]
__device__ __half g_vt[NZ * DH * BLK];           // v transposed [z][e][u]
__device__ __half g_Sh[NZ * BLK * BLK];          // masked QK^T fp16 [z][t][u]
__device__ __half g_kvt[NZ * DH * DH];           // scanned KV state transposed [z][e][d]
// fp16 operand buffers for projection GEMMs
__device__ __half g_hid_h[MROWS * HID];
__device__ __half g_wqkv_h[QKVC * HID];
__device__ __half g_wg_h[HID * HID];
__device__ __half g_wo_h[HID * HID];
__device__ __half g_gated_h[MROWS * HID];

__device__ __forceinline__ float sigmoidf_(float x) { return 1.f / (1.f + expf(-x)); }

// ---- side stream + fork/join events, created at static-init time.
static cudaStream_t g_sb = nullptr;
static cudaEvent_t  g_e1 = nullptr, g_e2 = nullptr;
namespace {
struct StreamInit {
    StreamInit() {
        if (cudaStreamCreateWithFlags(&g_sb, cudaStreamNonBlocking) != cudaSuccess) { g_sb = nullptr; return; }
        if (cudaEventCreateWithFlags(&g_e1, cudaEventDisableTiming) != cudaSuccess) { g_e1 = nullptr; }
        if (cudaEventCreateWithFlags(&g_e2, cudaEventDisableTiming) != cudaSuccess) { g_e2 = nullptr; }
    }
};
StreamInit g_stream_init;
}

// =================== PTX helpers (baseline compute_103 ISA only) =============
__device__ __forceinline__ uint32_t smem_u32(const void* p) {
    uint32_t a;
    asm("{ .reg .u64 t; cvta.to.shared.u64 t, %1; cvt.u32.u64 %0, t; }" : "=r"(a) : "l"(p));
    return a;
}
__device__ __forceinline__ void cpa16(uint32_t dst, const void* src) {
    asm volatile("cp.async.cg.shared.global [%0], [%1], 16;" :: "r"(dst), "l"(src) : "memory");
}
#define CP_COMMIT() asm volatile("cp.async.commit_group;" ::: "memory")
#define CP_WAIT1()  asm volatile("cp.async.wait_group 1;" ::: "memory")

__device__ __forceinline__ void ldm4(uint32_t* r, uint32_t addr) {
    asm volatile("ldmatrix.sync.aligned.m8n8.x4.shared.b16 {%0,%1,%2,%3}, [%4];"
        : "=r"(r[0]), "=r"(r[1]), "=r"(r[2]), "=r"(r[3]) : "r"(addr));
}
__device__ __forceinline__ void mma16816h(float* c, const uint32_t* a, const uint32_t* b) {
    asm volatile("mma.sync.aligned.m16n8k16.row.col.f32.f16.f16.f32 "
        "{%0,%1,%2,%3}, {%4,%5,%6,%7}, {%8,%9}, {%0,%1,%2,%3};"
        : "+f"(c[0]), "+f"(c[1]), "+f"(c[2]), "+f"(c[3])
        : "r"(a[0]), "r"(a[1]), "r"(a[2]), "r"(a[3]), "r"(b[0]), "r"(b[1]));
}

// ---------------- fp32 -> fp16 convert, vectorized ---------------------------
__global__ void __launch_bounds__(256) cvt_kernel(const float* __restrict__ src,
                                                  __half* __restrict__ dst, int n4) {
    int i = blockIdx.x * 256 + threadIdx.x;
    if (i >= n4) return;
    float4 v = ((const float4*)src)[i];
    __half2 a = __floats2half2_rn(v.x, v.y);
    __half2 b = __floats2half2_rn(v.z, v.w);
    uint2 u;
    u.x = *(uint32_t*)&a;
    u.y = *(uint32_t*)&b;
    ((uint2*)dst)[i] = u;
}

// ============== shared fp16 MMA tile pipeline (128x128 tile, 256 thr) ========
// K-chunk = 64, 2-stage double buffer. Smem tile: [128][72] fp16 (pad 8).
#define RS        72              // padded smem row stride (halves)
#define TILE_BYT  (128 * RS * 2)  // 18432
#define A_OFF     0
#define B_OFF     TILE_BYT
#define STG_BYT   (2 * TILE_BYT)  // 36864
#define SMEM_GEMM (2 * STG_BYT)   // 73728
#define RSTRIDE16 (16 * RS * 2)   // 2304 (16 smem rows)

// Accumulate C[128,128] += A[128, nch64*64] * B[128, nch64*64]^T (fp16, K-major).
__device__ __forceinline__ void mma_pipe(uint32_t sbase, int tid,
                                         const __half* gA, const __half* gB,
                                         int ast, int bst, int nch64,
                                         uint32_t aoff, uint32_t boff,
                                         float (*acc)[8][4]) {
    const int r = tid >> 1, h = tid & 1;
    const __half* ga = gA + (size_t)r * ast + h * 32;
    const __half* gb = gB + (size_t)r * bst + h * 32;
    const uint32_t sdst = (uint32_t)(r * (RS * 2) + h * 64);
    auto issue = [&](int c, int s) {
        const uint32_t st = sbase + (uint32_t)s * STG_BYT + sdst;
        const __half* pa = ga + c * 64;
        const __half* pb = gb + c * 64;
        cpa16(st + A_OFF,      pa);      cpa16(st + A_OFF + 16, pa + 8);
        cpa16(st + A_OFF + 32, pa + 16); cpa16(st + A_OFF + 48, pa + 24);
        cpa16(st + B_OFF,      pb);      cpa16(st + B_OFF + 16, pb + 8);
        cpa16(st + B_OFF + 32, pb + 16); cpa16(st + B_OFF + 48, pb + 24);
    };
    issue(0, 0); CP_COMMIT();
    if (nch64 > 1) issue(1, 1);
    CP_COMMIT();
    for (int i = 0; i < nch64; i++) {
        CP_WAIT1();
        __syncthreads();
        const uint32_t stage = sbase + (uint32_t)(i & 1) * STG_BYT;
#pragma unroll
        for (int ks = 0; ks < 4; ks++) {
            uint32_t ah[2][4];
            ldm4(ah[0], stage + A_OFF + aoff + ks * 32);
            ldm4(ah[1], stage + A_OFF + aoff + RSTRIDE16 + ks * 32);
#pragma unroll
            for (int pn = 0; pn < 4; pn++) {
                uint32_t bh4[4];
                ldm4(bh4, stage + B_OFF + boff + pn * RSTRIDE16 + ks * 32);
#pragma unroll
                for (int mt = 0; mt < 2; mt++)
#pragma unroll
                    for (int t2 = 0; t2 < 2; t2++)
                        mma16816h(acc[mt][pn * 2 + t2], ah[mt], bh4 + t2 * 2);
            }
        }
        __syncthreads();
        if (i + 2 < nch64) issue(i + 2, i & 1);
        CP_COMMIT();
    }
}
#define FRAG_OFFS(l, wm, wn, aoff, boff)                                            \
    const uint32_t aoff = (uint32_t)((((wm) * 32 + ((l) & 15)) * RS + (((l) >> 4) << 3)) * 2); \
    const uint32_t boff = (uint32_t)((((wn) * 64 + ((l) & 7) + (((l) >> 4) & 1) * 8) * RS     \
                                      + (((l) >> 3) & 1) * 8) * 2)

// ================== projection GEMMs =========================================
// MODE 0: silu -> fp16 g_qh/g_kh/g_vh (+ fused q*q_decay into g_qs);
// MODE 1: sigmoid -> g_gate; MODE 2: -> C.
template <int MODE>
__global__ void __launch_bounds__(256, 2) gemm_hmma(
    const __half* __restrict__ A, const __half* __restrict__ B,
    float* __restrict__ C, int K, int Ndim, const float* __restrict__ slope) {
    extern __shared__ char smem[];
    const uint32_t sbase = smem_u32(smem);
    const int tid = threadIdx.x;
    const int l = tid & 31, wid = tid >> 5;
    const int wm = wid & 3, wn = wid >> 2;
    const int n0 = blockIdx.x * 128;
    const int m0 = blockIdx.y * 128;
    FRAG_OFFS(l, wm, wn, aoff, boff);

    float acc[2][8][4];
#pragma unroll
    for (int a = 0; a < 2; a++)
#pragma unroll
        for (int b = 0; b < 8; b++)
#pragma unroll
            for (int c = 0; c < 4; c++) acc[a][b][c] = 0.f;

    mma_pipe(sbase, tid, A + (size_t)m0 * K, B + (size_t)n0 * K, K, K, K / 64,
             aoff, boff, acc);

    const int mbase = m0 + wm * 32 + (l >> 2);
    const int dbase = wn * 64 + (l & 3) * 2;
    __half* bp0h = nullptr;
    int hh = 0, mb = 0, sidx = 0;
    float sl = 0.f;
    if (MODE == 0) {
        sidx = n0 >> 11;
        hh = (n0 & 2047) >> 7;
        mb = m0 >> 12;
        bp0h = (sidx == 0) ? g_qh : ((sidx == 1) ? g_kh : g_vh);
        sl = slope[hh];
    }
#pragma unroll
    for (int mt = 0; mt < 2; mt++)
#pragma unroll
        for (int nt = 0; nt < 8; nt++) {
            const float* cc = acc[mt][nt];
#pragma unroll
            for (int rh = 0; rh < 2; rh++) {
                const int m1 = mbase + mt * 16 + rh * 8;
                float v0 = cc[rh * 2 + 0], v1 = cc[rh * 2 + 1];
                if (MODE == 0) {
                    v0 = v0 * sigmoidf_(v0);
                    v1 = v1 * sigmoidf_(v1);
                    const int nn = m1 & 4095;
                    const int d = dbase + nt * 8;
                    const size_t base = ((size_t)(mb * NHEAD + hh) * SEQ + nn) * DH + d;
                    *(__half2*)(bp0h + base) = __floats2half2_rn(v0, v1);
                    if (sidx == 0) {
                        const float qd = expf(-sl * (float)((nn & 255) + 1));
                        *(__half2*)(g_qs + base) = __floats2half2_rn(v0 * qd, v1 * qd);
                    }
                } else if (MODE == 1) {
                    *(float2*)(g_gate + (size_t)m1 * HID + n0 + dbase + nt * 8) =
                        make_float2(sigmoidf_(v0), sigmoidf_(v1));
                } else {
                    *(float2*)(C + (size_t)m1 * Ndim + n0 + dbase + nt * 8) =
                        make_float2(v0, v1);
                }
            }
        }
}

// ---------- transpose k (with k_decay) and v into [z][d][t] layout -----------
__global__ void __launch_bounds__(256) transpose_kernel(const float* __restrict__ slope) {
    const int which = blockIdx.x;           // 0 = k, 1 = v
    const int z = blockIdx.y;
    const int bh = z >> 4, blk = z & 15;
    const __half* src = (which ? g_vh : g_kh) + ((size_t)bh * SEQ + blk * BLK) * DH;
    __half* dst = (which ? g_vt : g_kt) + (size_t)z * DH * BLK;
    const float s = slope[bh & 15];
    __shared__ __half tile[64][72];
    const int r = threadIdx.x >> 2;          // 0..63
    const int c16 = (threadIdx.x & 3) * 16;  // 0,16,32,48
    for (int tc = 0; tc < 4; tc++) {
        for (int dc = 0; dc < 2; dc++) {
            const int t = tc * 64 + r;
            const float kd = which ? 1.f : expf(-s * (float)(255 - t));
            __half hv[16];
            *(uint4*)hv = *(const uint4*)(src + (size_t)t * DH + dc * 64 + c16);
            *(uint4*)(hv + 8) = *(const uint4*)(src + (size_t)t * DH + dc * 64 + c16 + 8);
            if (!which) {
#pragma unroll
                for (int j = 0; j < 16; j++)
                    hv[j] = __float2half_rn(__half2float(hv[j]) * kd);
            }
#pragma unroll
            for (int j = 0; j < 16; j++) tile[r][c16 + j] = hv[j];
            __syncthreads();
            __half ob[16];
#pragma unroll
            for (int j = 0; j < 16; j++) ob[j] = tile[c16 + j][r];
            __half* op = dst + (size_t)(dc * 64 + r) * BLK + tc * 64 + c16;
            *(uint4*)op = *(uint4*)ob;
            *(uint4*)(op + 8) = *(uint4*)(ob + 8);
            __syncthreads();
        }
    }
}

// ---------- per-block KV: C[d,e] = sum_t kt[d,t] * vt[e,t]  (fp16 MMA) -------
__global__ void __launch_bounds__(256, 2) kvblk_mma() {
    extern __shared__ char smem[];
    const uint32_t sbase = smem_u32(smem);
    const int tid = threadIdx.x;
    const int l = tid & 31, wid = tid >> 5;
    const int wm = wid & 3, wn = wid >> 2;
    const int z = blockIdx.x;
    FRAG_OFFS(l, wm, wn, aoff, boff);
    float acc[2][8][4];
#pragma unroll
    for (int a = 0; a < 2; a++)
#pragma unroll
        for (int b = 0; b < 8; b++)
#pragma unroll
            for (int c = 0; c < 4; c++) acc[a][b][c] = 0.f;
    mma_pipe(sbase, tid, g_kt + (size_t)z * DH * BLK, g_vt + (size_t)z * DH * BLK,
             BLK, BLK, BLK / 64, aoff, boff, acc);
    float* Co = g_kvblk + (size_t)z * DH * DH;
    const int mbase = wm * 32 + (l >> 2);
    const int dbase = wn * 64 + (l & 3) * 2;
#pragma unroll
    for (int mt = 0; mt < 2; mt++)
#pragma unroll
        for (int nt = 0; nt < 8; nt++)
#pragma unroll
            for (int rh = 0; rh < 2; rh++) {
                const int m1 = mbase + mt * 16 + rh * 8;
                *(float2*)(Co + (size_t)m1 * DH + dbase + nt * 8) =
                    make_float2(acc[mt][nt][rh * 2], acc[mt][nt][rh * 2 + 1]);
            }
}

// ---------- exclusive scan -> transposed fp16 kvstate ------------------------
__global__ void __launch_bounds__(256) scan_kernel(const float* __restrict__ slope) {
    const int bh = blockIdx.x >> 6;
    const int f = (blockIdx.x & 63) * 256 + threadIdx.x;  // f = d*128 + e
    const int d_ = f >> 7, e_ = f & 127;
    const float decay = expf(-slope[bh & 15] * (float)BLK);
    const float* src = g_kvblk + (size_t)bh * NB * DH * DH + f;
    __half* dstT = g_kvt + (size_t)bh * NB * DH * DH + e_ * DH + d_;
    float acc = 0.f;
#pragma unroll
    for (int i = 0; i < NB; i++) {
        dstT[(size_t)i * DH * DH] = __float2half_rn(acc);
        acc = decay * acc + src[(size_t)i * DH * DH];
    }
}

// ---------- S = (Q K^T) * causal decay -> fp16, 3 quadrants per z ------------
__global__ void __launch_bounds__(256, 2) qk_mma(const float* __restrict__ slope) {
    extern __shared__ char smem[];
    const uint32_t sbase = smem_u32(smem);
    const int tid = threadIdx.x;
    const int l = tid & 31, wid = tid >> 5;
    const int wm = wid & 3, wn = wid >> 2;
    const int z = blockIdx.y;
    const int quad = blockIdx.x;           // 0:(0,0) 1:(1,0) 2:(1,1)
    const int ti = (quad + 1) >> 1, ui = quad >> 1;
    const int bh = z >> 4, blk = z & 15;
    const float s = slope[bh & 15];
    FRAG_OFFS(l, wm, wn, aoff, boff);
    float acc[2][8][4];
#pragma unroll
    for (int a = 0; a < 2; a++)
#pragma unroll
        for (int b = 0; b < 8; b++)
#pragma unroll
            for (int c = 0; c < 4; c++) acc[a][b][c] = 0.f;
    mma_pipe(sbase, tid,
             g_qh + ((size_t)bh * SEQ + blk * BLK + ti * 128) * DH,
             g_kh + ((size_t)bh * SEQ + blk * BLK + ui * 128) * DH,
             DH, DH, DH / 64, aoff, boff, acc);
    __half* So = g_Sh + (size_t)z * BLK * BLK;
    const int mbase = wm * 32 + (l >> 2);
    const int dbase = wn * 64 + (l & 3) * 2;
#pragma unroll
    for (int mt = 0; mt < 2; mt++)
#pragma unroll
        for (int nt = 0; nt < 8; nt++)
#pragma unroll
            for (int rh = 0; rh < 2; rh++) {
                const int tt = ti * 128 + mbase + mt * 16 + rh * 8;
                const int u0 = ui * 128 + dbase + nt * 8;
                float v0 = (u0 <= tt) ? acc[mt][nt][rh * 2] * expf(-s * (float)(tt - u0)) : 0.f;
                float v1 = (u0 + 1 <= tt) ? acc[mt][nt][rh * 2 + 1] * expf(-s * (float)(tt - u0 - 1)) : 0.f;
                *(__half2*)(So + (size_t)tt * BLK + u0) = __floats2half2_rn(v0, v1);
            }
}

// ---------- out = q_s @ kvstate^T + S @ v^T  (fp16 MMA, 2 halves per z) ------
__global__ void __launch_bounds__(256, 2) attnout_mma() {
    extern __shared__ char smem[];
    const uint32_t sbase = smem_u32(smem);
    const int tid = threadIdx.x;
    const int l = tid & 31, wid = tid >> 5;
    const int wm = wid & 3, wn = wid >> 2;
    const int z = blockIdx.y;
    const int thalf = blockIdx.x;
    const int bh = z >> 4, blk = z & 15;
    FRAG_OFFS(l, wm, wn, aoff, boff);
    float acc[2][8][4];
#pragma unroll
    for (int a = 0; a < 2; a++)
#pragma unroll
        for (int b = 0; b < 8; b++)
#pragma unroll
            for (int c = 0; c < 4; c++) acc[a][b][c] = 0.f;
    // phase 1: inter = (q*qd) @ kvstate   (K = d = 128)
    mma_pipe(sbase, tid,
             g_qs + ((size_t)bh * SEQ + blk * BLK + thalf * 128) * DH,
             g_kvt + (size_t)z * DH * DH,
             DH, DH, DH / 64, aoff, boff, acc);
    __syncthreads();
    // phase 2: intra = S @ v   (K = u = 128 or 256)
    const int uend = thalf ? BLK : 128;
    mma_pipe(sbase, tid,
             g_Sh + (size_t)z * BLK * BLK + (size_t)(thalf * 128) * BLK,
             g_vt + (size_t)z * DH * BLK,
             BLK, BLK, uend / 64, aoff, boff, acc);
    const int mbase = wm * 32 + (l >> 2);
    const int dbase = wn * 64 + (l & 3) * 2;
#pragma unroll
    for (int mt = 0; mt < 2; mt++)
#pragma unroll
        for (int nt = 0; nt < 8; nt++)
#pragma unroll
            for (int rh = 0; rh < 2; rh++) {
                const int m1 = mbase + mt * 16 + rh * 8;
                const int nloc = blk * BLK + thalf * 128 + m1;
                *(float2*)(g_attn + ((size_t)bh * SEQ + nloc) * DH + dbase + nt * 8) =
                    make_float2(acc[mt][nt][rh * 2], acc[mt][nt][rh * 2 + 1]);
            }
}

// ------------- RMSNorm + gate -> gated fp16 (ready for out-GEMM) -------------
__global__ void __launch_bounds__(256) normgate_kernel(const float* __restrict__ norm_w) {
    const int row = blockIdx.x;
    const int bi = row >> 12;
    const int nn = row & 4095;
    const int tid = threadIdx.x;
    float vals[8];
    float ss = 0.f;
#pragma unroll
    for (int j0 = 0; j0 < 8; j0++) {
        const int j = tid + j0 * 256;
        const int hh = j >> 7, dd = j & 127;
        const float v = g_attn[((size_t)(bi * NHEAD + hh) * SEQ + nn) * DH + dd];
        vals[j0] = v;
        ss += v * v;
    }
#pragma unroll
    for (int o = 16; o > 0; o >>= 1) ss += __shfl_xor_sync(0xffffffffu, ss, o);
    __shared__ float red[8];
    __shared__ float scale_s;
    if ((tid & 31) == 0) red[tid >> 5] = ss;
    __syncthreads();
    if (tid == 0) {
        float t = 0.f;
#pragma unroll
        for (int w = 0; w < 8; w++) t += red[w];
        scale_s = rsqrtf(t / (float)HID + 1e-6f);
    }
    __syncthreads();
    const float sc = scale_s;
#pragma unroll
    for (int j0 = 0; j0 < 8; j0++) {
        const int j = tid + j0 * 256;
        const float v = g_gate[(size_t)row * HID + j] * vals[j0] * sc * norm_w[j];
        g_gated_h[(size_t)row * HID + j] = __float2half_rn(v);
    }
}

// --------------------------------- launch -----------------------------------
extern "C" void kernel_launch(void* const* d_in, const int* in_sizes, int n_in,
                              void* d_out, int out_size) {
    (void)in_sizes; (void)n_in; (void)out_size;
    const float* hidden = (const float*)d_in[0];
    const float* slope  = (const float*)d_in[1];
    const float* w_qkv  = (const float*)d_in[2];
    const float* w_gate = (const float*)d_in[3];
    const float* w_out  = (const float*)d_in[4];
    const float* norm_w = (const float*)d_in[5];
    float* out = (float*)d_out;

    cudaFuncSetAttribute(gemm_hmma<0>, cudaFuncAttributeMaxDynamicSharedMemorySize, SMEM_GEMM);
    cudaFuncSetAttribute(gemm_hmma<1>, cudaFuncAttributeMaxDynamicSharedMemorySize, SMEM_GEMM);
    cudaFuncSetAttribute(gemm_hmma<2>, cudaFuncAttributeMaxDynamicSharedMemorySize, SMEM_GEMM);
    cudaFuncSetAttribute(kvblk_mma,   cudaFuncAttributeMaxDynamicSharedMemorySize, SMEM_GEMM);
    cudaFuncSetAttribute(qk_mma,      cudaFuncAttributeMaxDynamicSharedMemorySize, SMEM_GEMM);
    cudaFuncSetAttribute(attnout_mma, cudaFuncAttributeMaxDynamicSharedMemorySize, SMEM_GEMM);

    __half *hid_h, *wq_h, *wg_h, *wo_h, *gd_h;
    cudaGetSymbolAddress((void**)&hid_h, g_hid_h);
    cudaGetSymbolAddress((void**)&wq_h, g_wqkv_h);
    cudaGetSymbolAddress((void**)&wg_h, g_wg_h);
    cudaGetSymbolAddress((void**)&wo_h, g_wo_h);
    cudaGetSymbolAddress((void**)&gd_h, g_gated_h);

    const bool fork = (g_sb != nullptr) && (g_e1 != nullptr) && (g_e2 != nullptr);

    // 0. fp32 -> fp16 conversions; gate/out weights on side stream (overlap
    //    with the QKV GEMM). Gate GEMM is on the same side stream afterward,
    //    so its operand ordering is implicit; join (e2) orders wo before gemm<2>.
    if (fork) {
        cvt_kernel<<<(HID * HID / 4 + 255) / 256, 256, 0, g_sb>>>(w_gate, wg_h, HID * HID / 4);
        cvt_kernel<<<(HID * HID / 4 + 255) / 256, 256, 0, g_sb>>>(w_out, wo_h, HID * HID / 4);
    } else {
        cvt_kernel<<<(HID * HID / 4 + 255) / 256, 256>>>(w_gate, wg_h, HID * HID / 4);
        cvt_kernel<<<(HID * HID / 4 + 255) / 256, 256>>>(w_out, wo_h, HID * HID / 4);
    }
    cvt_kernel<<<(MROWS * HID / 4 + 255) / 256, 256>>>(hidden, hid_h, MROWS * HID / 4);
    cvt_kernel<<<(QKVC * HID / 4 + 255) / 256, 256>>>(w_qkv, wq_h, QKVC * HID / 4);

    // 1. QKV projection + SiLU + fp16 scatter (+ fused q*q_decay)
    gemm_hmma<0><<<dim3(QKVC / 128, MROWS / 128), 256, SMEM_GEMM>>>(
        hid_h, wq_h, nullptr, HID, QKVC, slope);

    if (fork) {
        cudaEventRecord(g_e1, 0);
        cudaStreamWaitEvent(g_sb, g_e1, 0);
        gemm_hmma<1><<<dim3(HID / 128, MROWS / 128), 256, SMEM_GEMM, g_sb>>>(
            hid_h, wg_h, nullptr, HID, HID, slope);
        cudaEventRecord(g_e2, g_sb);
    }

    // 2. Lightning attention — all tensor-pipe fp16 MMA
    transpose_kernel<<<dim3(2, NZ), 256>>>(slope);
    kvblk_mma<<<NZ, 256, SMEM_GEMM>>>();
    scan_kernel<<<BHN * 64, 256>>>(slope);
    qk_mma<<<dim3(3, NZ), 256, SMEM_GEMM>>>(slope);
    attnout_mma<<<dim3(2, NZ), 256, SMEM_GEMM>>>();

    if (fork) {
        cudaStreamWaitEvent(0, g_e2, 0);   // JOIN
    } else {
        gemm_hmma<1><<<dim3(HID / 128, MROWS / 128), 256, SMEM_GEMM>>>(
            hid_h, wg_h, nullptr, HID, HID, slope);
    }

    // 4. RMSNorm + gate -> gated fp16
    normgate_kernel<<<MROWS, 256>>>(norm_w);
    // 5. Output projection
    gemm_hmma<2><<<dim3(HID / 128, MROWS / 128), 256, SMEM_GEMM>>>(
        gd_h, wo_h, out, HID, HID, slope);
}

// round 14
// speedup vs baseline: 1.1241x; 1.1241x over previous
#include <cuda_runtime.h>
#include <cuda_fp16.h>
#include <math.h>
#include <stdint.h>

// Problem constants (fixed shapes from reference)
#define BD     2
#define SEQ    4096
#define HID    2048
#define NHEAD  16
#define DH     128
#define BLK    256
#define NB     16          // SEQ/BLK
#define MROWS  8192        // BD*SEQ
#define QKVC   6144        // 3*HID
#define BHN    32          // BD*NHEAD
#define NZ     (BHN * NB)  // 512 (bh, blk) pairs

// ---------------- scratch (static device memory; no allocs allowed) ----------
__device__ float  g_attn[BHN * SEQ * DH];        // attention output (b,h,n,d) fp32
__device__ float  g_gate[MROWS * HID];           // sigmoid(x @ Wg^T)
__device__ float  g_kvblk[NZ * DH * DH];         // per-block KV contributions fp32
__device__ __half g_qh[BHN * SEQ * DH];          // q fp16 (b,h,n,d)
__device__ __half g_kh[BHN * SEQ * DH];
__device__ __half g_vh[BHN * SEQ * DH];
__device__ __half g_qs[BHN * SEQ * DH];          // q * q_decay fp16
__device__ __half g_kt[NZ * DH * BLK];           // k_decay*k transposed [z][d][t]
__device__ __half g_vt[NZ * DH * BLK];           // v transposed [z][e][u]
__device__ __half g_Sh[NZ * BLK * BLK];          // masked QK^T fp16 [z][t][u]
__device__ __half g_kvt[NZ * DH * DH];           // scanned KV state transposed [z][e][d]
// fp16 operand buffers for projection GEMMs
__device__ __half g_hid_h[MROWS * HID];
__device__ __half g_wqkv_h[QKVC * HID];
__device__ __half g_wg_h[HID * HID];
__device__ __half g_wo_h[HID * HID];
__device__ __half g_gated_h[MROWS * HID];

__device__ __forceinline__ float sigmoidf_(float x) { return 1.f / (1.f + expf(-x)); }

// ---- side stream + fork/join events, created at static-init time.
static cudaStream_t g_sb = nullptr;
static cudaEvent_t  g_e1 = nullptr, g_e2 = nullptr;
namespace {
struct StreamInit {
    StreamInit() {
        if (cudaStreamCreateWithFlags(&g_sb, cudaStreamNonBlocking) != cudaSuccess) { g_sb = nullptr; return; }
        if (cudaEventCreateWithFlags(&g_e1, cudaEventDisableTiming) != cudaSuccess) { g_e1 = nullptr; }
        if (cudaEventCreateWithFlags(&g_e2, cudaEventDisableTiming) != cudaSuccess) { g_e2 = nullptr; }
    }
};
StreamInit g_stream_init;
}

// =================== PTX helpers (baseline compute_103 ISA only) =============
__device__ __forceinline__ uint32_t smem_u32(const void* p) {
    uint32_t a;
    asm("{ .reg .u64 t; cvta.to.shared.u64 t, %1; cvt.u32.u64 %0, t; }" : "=r"(a) : "l"(p));
    return a;
}
__device__ __forceinline__ void cpa16(uint32_t dst, const void* src) {
    asm volatile("cp.async.cg.shared.global [%0], [%1], 16;" :: "r"(dst), "l"(src) : "memory");
}
#define CP_COMMIT() asm volatile("cp.async.commit_group;" ::: "memory")
#define CP_WAIT1()  asm volatile("cp.async.wait_group 1;" ::: "memory")

__device__ __forceinline__ void ldm4(uint32_t* r, uint32_t addr) {
    asm volatile("ldmatrix.sync.aligned.m8n8.x4.shared.b16 {%0,%1,%2,%3}, [%4];"
        : "=r"(r[0]), "=r"(r[1]), "=r"(r[2]), "=r"(r[3]) : "r"(addr));
}
__device__ __forceinline__ void mma16816h(float* c, const uint32_t* a, const uint32_t* b) {
    asm volatile("mma.sync.aligned.m16n8k16.row.col.f32.f16.f16.f32 "
        "{%0,%1,%2,%3}, {%4,%5,%6,%7}, {%8,%9}, {%0,%1,%2,%3};"
        : "+f"(c[0]), "+f"(c[1]), "+f"(c[2]), "+f"(c[3])
        : "r"(a[0]), "r"(a[1]), "r"(a[2]), "r"(a[3]), "r"(b[0]), "r"(b[1]));
}

// ---------------- fp32 -> fp16 convert, vectorized ---------------------------
__global__ void __launch_bounds__(256) cvt_kernel(const float* __restrict__ src,
                                                  __half* __restrict__ dst, int n4) {
    int i = blockIdx.x * 256 + threadIdx.x;
    if (i >= n4) return;
    float4 v = ((const float4*)src)[i];
    __half2 a = __floats2half2_rn(v.x, v.y);
    __half2 b = __floats2half2_rn(v.z, v.w);
    uint2 u;
    u.x = *(uint32_t*)&a;
    u.y = *(uint32_t*)&b;
    ((uint2*)dst)[i] = u;
}

// ============== shared fp16 MMA tile pipeline (128x128 tile, 256 thr) ========
// 3-stage cp.async pipeline, K-chunk = 32 (round-12 proven configuration).
#define RS        40              // padded smem row stride (halves)
#define TILE_BYT  (128 * RS * 2)  // 10240
#define A_OFF     0
#define B_OFF     TILE_BYT
#define STG_BYT   (2 * TILE_BYT)  // 20480
#define SMEM_GEMM (3 * STG_BYT)   // 61440

// Accumulate C[128,128] += A[128, nch*32] * B[128, nch*32]^T (fp16, K-major).
__device__ __forceinline__ void mma_pipe(uint32_t sbase, int tid,
                                         const __half* gA, const __half* gB,
                                         int ast, int bst, int nch,
                                         uint32_t aoff, uint32_t boff,
                                         float (*acc)[8][4]) {
    const int r = tid >> 1, h = tid & 1;
    const __half* ga = gA + (size_t)r * ast + h * 16;
    const __half* gb = gB + (size_t)r * bst + h * 16;
    const uint32_t sdst = (uint32_t)(r * (RS * 2) + h * 32);
    auto issue = [&](int c, int s) {
        const uint32_t st = sbase + (uint32_t)s * STG_BYT + sdst;
        cpa16(st + A_OFF,      ga + c * 32); cpa16(st + A_OFF + 16, ga + c * 32 + 8);
        cpa16(st + B_OFF,      gb + c * 32); cpa16(st + B_OFF + 16, gb + c * 32 + 8);
    };
    issue(0, 0); CP_COMMIT();
    issue(1, 1); CP_COMMIT();
    for (int i = 0; i < nch; i++) {
        const int s = i % 3;
        CP_WAIT1();
        __syncthreads();
        if (i + 2 < nch) issue(i + 2, (i + 2) % 3);
        CP_COMMIT();
        const uint32_t stage = sbase + (uint32_t)s * STG_BYT;
#pragma unroll
        for (int ks = 0; ks < 2; ks++) {
            uint32_t ah[2][4];
            ldm4(ah[0], stage + A_OFF + aoff + ks * 32);
            ldm4(ah[1], stage + A_OFF + aoff + 1280 + ks * 32);
#pragma unroll
            for (int pn = 0; pn < 4; pn++) {
                uint32_t bh4[4];
                ldm4(bh4, stage + B_OFF + boff + pn * 1280 + ks * 32);
#pragma unroll
                for (int mt = 0; mt < 2; mt++)
#pragma unroll
                    for (int t2 = 0; t2 < 2; t2++)
                        mma16816h(acc[mt][pn * 2 + t2], ah[mt], bh4 + t2 * 2);
            }
        }
    }
}
#define FRAG_OFFS(l, wm, wn, aoff, boff)                                            \
    const uint32_t aoff = (uint32_t)((((wm) * 32 + ((l) & 15)) * RS + (((l) >> 4) << 3)) * 2); \
    const uint32_t boff = (uint32_t)((((wn) * 64 + ((l) & 7) + (((l) >> 4) & 1) * 8) * RS     \
                                      + (((l) >> 3) & 1) * 8) * 2)

// ================== projection GEMMs =========================================
// MODE 0: silu -> fp16 g_qh/g_kh/g_vh (+ fused q*q_decay into g_qs);
// MODE 1: sigmoid -> g_gate; MODE 2: -> C.
template <int MODE>
__global__ void __launch_bounds__(256, 2) gemm_hmma(
    const __half* __restrict__ A, const __half* __restrict__ B,
    float* __restrict__ C, int K, int Ndim, const float* __restrict__ slope) {
    extern __shared__ char smem[];
    const uint32_t sbase = smem_u32(smem);
    const int tid = threadIdx.x;
    const int l = tid & 31, wid = tid >> 5;
    const int wm = wid & 3, wn = wid >> 2;
    const int n0 = blockIdx.x * 128;
    const int m0 = blockIdx.y * 128;
    FRAG_OFFS(l, wm, wn, aoff, boff);

    float acc[2][8][4];
#pragma unroll
    for (int a = 0; a < 2; a++)
#pragma unroll
        for (int b = 0; b < 8; b++)
#pragma unroll
            for (int c = 0; c < 4; c++) acc[a][b][c] = 0.f;

    mma_pipe(sbase, tid, A + (size_t)m0 * K, B + (size_t)n0 * K, K, K, K / 32,
             aoff, boff, acc);

    const int mbase = m0 + wm * 32 + (l >> 2);
    const int dbase = wn * 64 + (l & 3) * 2;
    __half* bp0h = nullptr;
    int hh = 0, mb = 0, sidx = 0;
    float sl = 0.f;
    if (MODE == 0) {
        sidx = n0 >> 11;
        hh = (n0 & 2047) >> 7;
        mb = m0 >> 12;
        bp0h = (sidx == 0) ? g_qh : ((sidx == 1) ? g_kh : g_vh);
        sl = slope[hh];
    }
#pragma unroll
    for (int mt = 0; mt < 2; mt++)
#pragma unroll
        for (int nt = 0; nt < 8; nt++) {
            const float* cc = acc[mt][nt];
#pragma unroll
            for (int rh = 0; rh < 2; rh++) {
                const int m1 = mbase + mt * 16 + rh * 8;
                float v0 = cc[rh * 2 + 0], v1 = cc[rh * 2 + 1];
                if (MODE == 0) {
                    v0 = v0 * sigmoidf_(v0);
                    v1 = v1 * sigmoidf_(v1);
                    const int nn = m1 & 4095;
                    const int d = dbase + nt * 8;
                    const size_t base = ((size_t)(mb * NHEAD + hh) * SEQ + nn) * DH + d;
                    *(__half2*)(bp0h + base) = __floats2half2_rn(v0, v1);
                    if (sidx == 0) {
                        const float qd = expf(-sl * (float)((nn & 255) + 1));
                        *(__half2*)(g_qs + base) = __floats2half2_rn(v0 * qd, v1 * qd);
                    }
                } else if (MODE == 1) {
                    *(float2*)(g_gate + (size_t)m1 * HID + n0 + dbase + nt * 8) =
                        make_float2(sigmoidf_(v0), sigmoidf_(v1));
                } else {
                    *(float2*)(C + (size_t)m1 * Ndim + n0 + dbase + nt * 8) =
                        make_float2(v0, v1);
                }
            }
        }
}

// ---------- transpose k (with k_decay) and v into [z][d][t] layout -----------
__global__ void __launch_bounds__(256) transpose_kernel(const float* __restrict__ slope) {
    const int which = blockIdx.x;           // 0 = k, 1 = v
    const int z = blockIdx.y;
    const int bh = z >> 4, blk = z & 15;
    const __half* src = (which ? g_vh : g_kh) + ((size_t)bh * SEQ + blk * BLK) * DH;
    __half* dst = (which ? g_vt : g_kt) + (size_t)z * DH * BLK;
    const float s = slope[bh & 15];
    __shared__ __half tile[64][72];
    const int r = threadIdx.x >> 2;          // 0..63
    const int c16 = (threadIdx.x & 3) * 16;  // 0,16,32,48
    for (int tc = 0; tc < 4; tc++) {
        for (int dc = 0; dc < 2; dc++) {
            const int t = tc * 64 + r;
            const float kd = which ? 1.f : expf(-s * (float)(255 - t));
            __half hv[16];
            *(uint4*)hv = *(const uint4*)(src + (size_t)t * DH + dc * 64 + c16);
            *(uint4*)(hv + 8) = *(const uint4*)(src + (size_t)t * DH + dc * 64 + c16 + 8);
            if (!which) {
#pragma unroll
                for (int j = 0; j < 16; j++)
                    hv[j] = __float2half_rn(__half2float(hv[j]) * kd);
            }
#pragma unroll
            for (int j = 0; j < 16; j++) tile[r][c16 + j] = hv[j];
            __syncthreads();
            __half ob[16];
#pragma unroll
            for (int j = 0; j < 16; j++) ob[j] = tile[c16 + j][r];
            __half* op = dst + (size_t)(dc * 64 + r) * BLK + tc * 64 + c16;
            *(uint4*)op = *(uint4*)ob;
            *(uint4*)(op + 8) = *(uint4*)(ob + 8);
            __syncthreads();
        }
    }
}

// ---------- per-block KV: C[d,e] = sum_t kt[d,t] * vt[e,t]  (fp16 MMA) -------
__global__ void __launch_bounds__(256, 2) kvblk_mma() {
    extern __shared__ char smem[];
    const uint32_t sbase = smem_u32(smem);
    const int tid = threadIdx.x;
    const int l = tid & 31, wid = tid >> 5;
    const int wm = wid & 3, wn = wid >> 2;
    const int z = blockIdx.x;
    FRAG_OFFS(l, wm, wn, aoff, boff);
    float acc[2][8][4];
#pragma unroll
    for (int a = 0; a < 2; a++)
#pragma unroll
        for (int b = 0; b < 8; b++)
#pragma unroll
            for (int c = 0; c < 4; c++) acc[a][b][c] = 0.f;
    mma_pipe(sbase, tid, g_kt + (size_t)z * DH * BLK, g_vt + (size_t)z * DH * BLK,
             BLK, BLK, BLK / 32, aoff, boff, acc);
    float* Co = g_kvblk + (size_t)z * DH * DH;
    const int mbase = wm * 32 + (l >> 2);
    const int dbase = wn * 64 + (l & 3) * 2;
#pragma unroll
    for (int mt = 0; mt < 2; mt++)
#pragma unroll
        for (int nt = 0; nt < 8; nt++)
#pragma unroll
            for (int rh = 0; rh < 2; rh++) {
                const int m1 = mbase + mt * 16 + rh * 8;
                *(float2*)(Co + (size_t)m1 * DH + dbase + nt * 8) =
                    make_float2(acc[mt][nt][rh * 2], acc[mt][nt][rh * 2 + 1]);
            }
}

// ---------- exclusive scan -> transposed fp16 kvstate ------------------------
__global__ void __launch_bounds__(256) scan_kernel(const float* __restrict__ slope) {
    const int bh = blockIdx.x >> 6;
    const int f = (blockIdx.x & 63) * 256 + threadIdx.x;  // f = d*128 + e
    const int d_ = f >> 7, e_ = f & 127;
    const float decay = expf(-slope[bh & 15] * (float)BLK);
    const float* src = g_kvblk + (size_t)bh * NB * DH * DH + f;
    __half* dstT = g_kvt + (size_t)bh * NB * DH * DH + e_ * DH + d_;
    float acc = 0.f;
#pragma unroll
    for (int i = 0; i < NB; i++) {
        dstT[(size_t)i * DH * DH] = __float2half_rn(acc);
        acc = decay * acc + src[(size_t)i * DH * DH];
    }
}

// ---------- S = (Q K^T) * causal decay -> fp16, 3 quadrants per z ------------
__global__ void __launch_bounds__(256, 2) qk_mma(const float* __restrict__ slope) {
    extern __shared__ char smem[];
    const uint32_t sbase = smem_u32(smem);
    const int tid = threadIdx.x;
    const int l = tid & 31, wid = tid >> 5;
    const int wm = wid & 3, wn = wid >> 2;
    const int z = blockIdx.y;
    const int quad = blockIdx.x;           // 0:(0,0) 1:(1,0) 2:(1,1)
    const int ti = (quad + 1) >> 1, ui = quad >> 1;
    const int bh = z >> 4, blk = z & 15;
    const float s = slope[bh & 15];
    FRAG_OFFS(l, wm, wn, aoff, boff);
    float acc[2][8][4];
#pragma unroll
    for (int a = 0; a < 2; a++)
#pragma unroll
        for (int b = 0; b < 8; b++)
#pragma unroll
            for (int c = 0; c < 4; c++) acc[a][b][c] = 0.f;
    mma_pipe(sbase, tid,
             g_qh + ((size_t)bh * SEQ + blk * BLK + ti * 128) * DH,
             g_kh + ((size_t)bh * SEQ + blk * BLK + ui * 128) * DH,
             DH, DH, DH / 32, aoff, boff, acc);
    __half* So = g_Sh + (size_t)z * BLK * BLK;
    const int mbase = wm * 32 + (l >> 2);
    const int dbase = wn * 64 + (l & 3) * 2;
#pragma unroll
    for (int mt = 0; mt < 2; mt++)
#pragma unroll
        for (int nt = 0; nt < 8; nt++)
#pragma unroll
            for (int rh = 0; rh < 2; rh++) {
                const int tt = ti * 128 + mbase + mt * 16 + rh * 8;
                const int u0 = ui * 128 + dbase + nt * 8;
                float v0 = (u0 <= tt) ? acc[mt][nt][rh * 2] * expf(-s * (float)(tt - u0)) : 0.f;
                float v1 = (u0 + 1 <= tt) ? acc[mt][nt][rh * 2 + 1] * expf(-s * (float)(tt - u0 - 1)) : 0.f;
                *(__half2*)(So + (size_t)tt * BLK + u0) = __floats2half2_rn(v0, v1);
            }
}

// ---------- out = q_s @ kvstate^T + S @ v^T  (fp16 MMA, 2 halves per z) ------
__global__ void __launch_bounds__(256, 2) attnout_mma() {
    extern __shared__ char smem[];
    const uint32_t sbase = smem_u32(smem);
    const int tid = threadIdx.x;
    const int l = tid & 31, wid = tid >> 5;
    const int wm = wid & 3, wn = wid >> 2;
    const int z = blockIdx.y;
    const int thalf = blockIdx.x;
    const int bh = z >> 4, blk = z & 15;
    FRAG_OFFS(l, wm, wn, aoff, boff);
    float acc[2][8][4];
#pragma unroll
    for (int a = 0; a < 2; a++)
#pragma unroll
        for (int b = 0; b < 8; b++)
#pragma unroll
            for (int c = 0; c < 4; c++) acc[a][b][c] = 0.f;
    // phase 1: inter = (q*qd) @ kvstate   (K = d = 128)
    mma_pipe(sbase, tid,
             g_qs + ((size_t)bh * SEQ + blk * BLK + thalf * 128) * DH,
             g_kvt + (size_t)z * DH * DH,
             DH, DH, DH / 32, aoff, boff, acc);
    __syncthreads();
    // phase 2: intra = S @ v   (K = u = 128 or 256)
    const int uend = thalf ? BLK : 128;
    mma_pipe(sbase, tid,
             g_Sh + (size_t)z * BLK * BLK + (size_t)(thalf * 128) * BLK,
             g_vt + (size_t)z * DH * BLK,
             BLK, BLK, uend / 32, aoff, boff, acc);
    const int mbase = wm * 32 + (l >> 2);
    const int dbase = wn * 64 + (l & 3) * 2;
#pragma unroll
    for (int mt = 0; mt < 2; mt++)
#pragma unroll
        for (int nt = 0; nt < 8; nt++)
#pragma unroll
            for (int rh = 0; rh < 2; rh++) {
                const int m1 = mbase + mt * 16 + rh * 8;
                const int nloc = blk * BLK + thalf * 128 + m1;
                *(float2*)(g_attn + ((size_t)bh * SEQ + nloc) * DH + dbase + nt * 8) =
                    make_float2(acc[mt][nt][rh * 2], acc[mt][nt][rh * 2 + 1]);
            }
}

// ------------- RMSNorm + gate -> gated fp16 (ready for out-GEMM) -------------
__global__ void __launch_bounds__(256) normgate_kernel(const float* __restrict__ norm_w) {
    const int row = blockIdx.x;
    const int bi = row >> 12;
    const int nn = row & 4095;
    const int tid = threadIdx.x;
    float vals[8];
    float ss = 0.f;
#pragma unroll
    for (int j0 = 0; j0 < 8; j0++) {
        const int j = tid + j0 * 256;
        const int hh = j >> 7, dd = j & 127;
        const float v = g_attn[((size_t)(bi * NHEAD + hh) * SEQ + nn) * DH + dd];
        vals[j0] = v;
        ss += v * v;
    }
#pragma unroll
    for (int o = 16; o > 0; o >>= 1) ss += __shfl_xor_sync(0xffffffffu, ss, o);
    __shared__ float red[8];
    __shared__ float scale_s;
    if ((tid & 31) == 0) red[tid >> 5] = ss;
    __syncthreads();
    if (tid == 0) {
        float t = 0.f;
#pragma unroll
        for (int w = 0; w < 8; w++) t += red[w];
        scale_s = rsqrtf(t / (float)HID + 1e-6f);
    }
    __syncthreads();
    const float sc = scale_s;
#pragma unroll
    for (int j0 = 0; j0 < 8; j0++) {
        const int j = tid + j0 * 256;
        const float v = g_gate[(size_t)row * HID + j] * vals[j0] * sc * norm_w[j];
        g_gated_h[(size_t)row * HID + j] = __float2half_rn(v);
    }
}

// --------------------------------- launch -----------------------------------
extern "C" void kernel_launch(void* const* d_in, const int* in_sizes, int n_in,
                              void* d_out, int out_size) {
    (void)in_sizes; (void)n_in; (void)out_size;
    const float* hidden = (const float*)d_in[0];
    const float* slope  = (const float*)d_in[1];
    const float* w_qkv  = (const float*)d_in[2];
    const float* w_gate = (const float*)d_in[3];
    const float* w_out  = (const float*)d_in[4];
    const float* norm_w = (const float*)d_in[5];
    float* out = (float*)d_out;

    cudaFuncSetAttribute(gemm_hmma<0>, cudaFuncAttributeMaxDynamicSharedMemorySize, SMEM_GEMM);
    cudaFuncSetAttribute(gemm_hmma<1>, cudaFuncAttributeMaxDynamicSharedMemorySize, SMEM_GEMM);
    cudaFuncSetAttribute(gemm_hmma<2>, cudaFuncAttributeMaxDynamicSharedMemorySize, SMEM_GEMM);
    cudaFuncSetAttribute(kvblk_mma,   cudaFuncAttributeMaxDynamicSharedMemorySize, SMEM_GEMM);
    cudaFuncSetAttribute(qk_mma,      cudaFuncAttributeMaxDynamicSharedMemorySize, SMEM_GEMM);
    cudaFuncSetAttribute(attnout_mma, cudaFuncAttributeMaxDynamicSharedMemorySize, SMEM_GEMM);

    __half *hid_h, *wq_h, *wg_h, *wo_h, *gd_h;
    cudaGetSymbolAddress((void**)&hid_h, g_hid_h);
    cudaGetSymbolAddress((void**)&wq_h, g_wqkv_h);
    cudaGetSymbolAddress((void**)&wg_h, g_wg_h);
    cudaGetSymbolAddress((void**)&wo_h, g_wo_h);
    cudaGetSymbolAddress((void**)&gd_h, g_gated_h);

    const bool fork = (g_sb != nullptr) && (g_e1 != nullptr) && (g_e2 != nullptr);

    // 0. fp32 -> fp16 conversions; gate/out weights on side stream (overlap
    //    with the QKV GEMM). Gate GEMM follows on the same side stream, so its
    //    operand ordering is implicit; the join (e2) orders wo before gemm<2>.
    if (fork) {
        cvt_kernel<<<(HID * HID / 4 + 255) / 256, 256, 0, g_sb>>>(w_gate, wg_h, HID * HID / 4);
        cvt_kernel<<<(HID * HID / 4 + 255) / 256, 256, 0, g_sb>>>(w_out, wo_h, HID * HID / 4);
    } else {
        cvt_kernel<<<(HID * HID / 4 + 255) / 256, 256>>>(w_gate, wg_h, HID * HID / 4);
        cvt_kernel<<<(HID * HID / 4 + 255) / 256, 256>>>(w_out, wo_h, HID * HID / 4);
    }
    cvt_kernel<<<(MROWS * HID / 4 + 255) / 256, 256>>>(hidden, hid_h, MROWS * HID / 4);
    cvt_kernel<<<(QKVC * HID / 4 + 255) / 256, 256>>>(w_qkv, wq_h, QKVC * HID / 4);

    // 1. QKV projection + SiLU + fp16 scatter (+ fused q*q_decay)
    gemm_hmma<0><<<dim3(QKVC / 128, MROWS / 128), 256, SMEM_GEMM>>>(
        hid_h, wq_h, nullptr, HID, QKVC, slope);

    if (fork) {
        cudaEventRecord(g_e1, 0);
        cudaStreamWaitEvent(g_sb, g_e1, 0);
        gemm_hmma<1><<<dim3(HID / 128, MROWS / 128), 256, SMEM_GEMM, g_sb>>>(
            hid_h, wg_h, nullptr, HID, HID, slope);
        cudaEventRecord(g_e2, g_sb);
    }

    // 2. Lightning attention — all tensor-pipe fp16 MMA
    transpose_kernel<<<dim3(2, NZ), 256>>>(slope);
    kvblk_mma<<<NZ, 256, SMEM_GEMM>>>();
    scan_kernel<<<BHN * 64, 256>>>(slope);
    qk_mma<<<dim3(3, NZ), 256, SMEM_GEMM>>>(slope);
    attnout_mma<<<dim3(2, NZ), 256, SMEM_GEMM>>>();

    if (fork) {
        cudaStreamWaitEvent(0, g_e2, 0);   // JOIN
    } else {
        gemm_hmma<1><<<dim3(HID / 128, MROWS / 128), 256, SMEM_GEMM>>>(
            hid_h, wg_h, nullptr, HID, HID, slope);
    }

    // 4. RMSNorm + gate -> gated fp16
    normgate_kernel<<<MROWS, 256>>>(norm_w);
    // 5. Output projection
    gemm_hmma<2><<<dim3(HID / 128, MROWS / 128), 256, SMEM_GEMM>>>(
        gd_h, wo_h, out, HID, HID, slope);
}

// round 15
// speedup vs baseline: 1.1357x; 1.0103x over previous
#include <cuda_runtime.h>
#include <cuda_fp16.h>
#include <math.h>
#include <stdint.h>

// Problem constants (fixed shapes from reference)
#define BD     2
#define SEQ    4096
#define HID    2048
#define NHEAD  16
#define DH     128
#define BLK    256
#define NB     16          // SEQ/BLK
#define MROWS  8192        // BD*SEQ
#define QKVC   6144        // 3*HID
#define BHN    32          // BD*NHEAD
#define NZ     (BHN * NB)  // 512 (bh, blk) pairs

// ---------------- scratch (static device memory; no allocs allowed) ----------
__device__ __half g_attn[BHN * SEQ * DH];        // attention output (b,h,n,d) fp16
__device__ __half g_gate[MROWS * HID];           // sigmoid(x @ Wg^T) fp16
__device__ float  g_kvblk[NZ * DH * DH];         // per-block KV contributions fp32
__device__ __half g_qh[BHN * SEQ * DH];          // q fp16 (b,h,n,d)
__device__ __half g_kh[BHN * SEQ * DH];
__device__ __half g_vh[BHN * SEQ * DH];
__device__ __half g_qs[BHN * SEQ * DH];          // q * q_decay fp16
__device__ __half g_kt[NZ * DH * BLK];           // k_decay*k transposed [z][d][t]
__device__ __half g_vt[NZ * DH * BLK];           // v transposed [z][e][u]
__device__ __half g_Sh[NZ * BLK * BLK];          // masked QK^T fp16 [z][t][u]
__device__ __half g_kvt[NZ * DH * DH];           // scanned KV state transposed [z][e][d]
// fp16 operand buffers for projection GEMMs
__device__ __half g_hid_h[MROWS * HID];
__device__ __half g_wqkv_h[QKVC * HID];
__device__ __half g_wg_h[HID * HID];
__device__ __half g_wo_h[HID * HID];
__device__ __half g_gated_h[MROWS * HID];

__device__ __forceinline__ float sigmoidf_(float x) { return 1.f / (1.f + expf(-x)); }

// ---- side stream + fork/join events, created at static-init time.
static cudaStream_t g_sb = nullptr;
static cudaEvent_t  g_e1 = nullptr, g_e2 = nullptr, g_e3 = nullptr;
namespace {
struct StreamInit {
    StreamInit() {
        if (cudaStreamCreateWithFlags(&g_sb, cudaStreamNonBlocking) != cudaSuccess) { g_sb = nullptr; return; }
        if (cudaEventCreateWithFlags(&g_e1, cudaEventDisableTiming) != cudaSuccess) { g_e1 = nullptr; }
        if (cudaEventCreateWithFlags(&g_e2, cudaEventDisableTiming) != cudaSuccess) { g_e2 = nullptr; }
        if (cudaEventCreateWithFlags(&g_e3, cudaEventDisableTiming) != cudaSuccess) { g_e3 = nullptr; }
    }
};
StreamInit g_stream_init;
}

// =================== PTX helpers (baseline compute_103 ISA only) =============
__device__ __forceinline__ uint32_t smem_u32(const void* p) {
    uint32_t a;
    asm("{ .reg .u64 t; cvta.to.shared.u64 t, %1; cvt.u32.u64 %0, t; }" : "=r"(a) : "l"(p));
    return a;
}
__device__ __forceinline__ void cpa16(uint32_t dst, const void* src) {
    asm volatile("cp.async.cg.shared.global [%0], [%1], 16;" :: "r"(dst), "l"(src) : "memory");
}
#define CP_COMMIT() asm volatile("cp.async.commit_group;" ::: "memory")
#define CP_WAIT1()  asm volatile("cp.async.wait_group 1;" ::: "memory")

__device__ __forceinline__ void ldm4(uint32_t* r, uint32_t addr) {
    asm volatile("ldmatrix.sync.aligned.m8n8.x4.shared.b16 {%0,%1,%2,%3}, [%4];"
        : "=r"(r[0]), "=r"(r[1]), "=r"(r[2]), "=r"(r[3]) : "r"(addr));
}
__device__ __forceinline__ void mma16816h(float* c, const uint32_t* a, const uint32_t* b) {
    asm volatile("mma.sync.aligned.m16n8k16.row.col.f32.f16.f16.f32 "
        "{%0,%1,%2,%3}, {%4,%5,%6,%7}, {%8,%9}, {%0,%1,%2,%3};"
        : "+f"(c[0]), "+f"(c[1]), "+f"(c[2]), "+f"(c[3])
        : "r"(a[0]), "r"(a[1]), "r"(a[2]), "r"(a[3]), "r"(b[0]), "r"(b[1]));
}

// ---------------- fp32 -> fp16 convert, vectorized ---------------------------
__global__ void __launch_bounds__(256) cvt_kernel(const float* __restrict__ src,
                                                  __half* __restrict__ dst, int n4) {
    int i = blockIdx.x * 256 + threadIdx.x;
    if (i >= n4) return;
    float4 v = ((const float4*)src)[i];
    __half2 a = __floats2half2_rn(v.x, v.y);
    __half2 b = __floats2half2_rn(v.z, v.w);
    uint2 u;
    u.x = *(uint32_t*)&a;
    u.y = *(uint32_t*)&b;
    ((uint2*)dst)[i] = u;
}

// ============== shared fp16 MMA tile pipeline (128x128 tile, 256 thr) ========
// 3-stage cp.async pipeline, K-chunk = 32 (proven configuration).
#define RS        40              // padded smem row stride (halves)
#define TILE_BYT  (128 * RS * 2)  // 10240
#define A_OFF     0
#define B_OFF     TILE_BYT
#define STG_BYT   (2 * TILE_BYT)  // 20480
#define SMEM_GEMM (3 * STG_BYT)   // 61440

// Accumulate C[128,128] += A[128, nch*32] * B[128, nch*32]^T (fp16, K-major).
__device__ __forceinline__ void mma_pipe(uint32_t sbase, int tid,
                                         const __half* gA, const __half* gB,
                                         int ast, int bst, int nch,
                                         uint32_t aoff, uint32_t boff,
                                         float (*acc)[8][4]) {
    const int r = tid >> 1, h = tid & 1;
    const __half* ga = gA + (size_t)r * ast + h * 16;
    const __half* gb = gB + (size_t)r * bst + h * 16;
    const uint32_t sdst = (uint32_t)(r * (RS * 2) + h * 32);
    auto issue = [&](int c, int s) {
        const uint32_t st = sbase + (uint32_t)s * STG_BYT + sdst;
        cpa16(st + A_OFF,      ga + c * 32); cpa16(st + A_OFF + 16, ga + c * 32 + 8);
        cpa16(st + B_OFF,      gb + c * 32); cpa16(st + B_OFF + 16, gb + c * 32 + 8);
    };
    issue(0, 0); CP_COMMIT();
    issue(1, 1); CP_COMMIT();
    for (int i = 0; i < nch; i++) {
        const int s = i % 3;
        CP_WAIT1();
        __syncthreads();
        if (i + 2 < nch) issue(i + 2, (i + 2) % 3);
        CP_COMMIT();
        const uint32_t stage = sbase + (uint32_t)s * STG_BYT;
#pragma unroll
        for (int ks = 0; ks < 2; ks++) {
            uint32_t ah[2][4];
            ldm4(ah[0], stage + A_OFF + aoff + ks * 32);
            ldm4(ah[1], stage + A_OFF + aoff + 1280 + ks * 32);
#pragma unroll
            for (int pn = 0; pn < 4; pn++) {
                uint32_t bh4[4];
                ldm4(bh4, stage + B_OFF + boff + pn * 1280 + ks * 32);
#pragma unroll
                for (int mt = 0; mt < 2; mt++)
#pragma unroll
                    for (int t2 = 0; t2 < 2; t2++)
                        mma16816h(acc[mt][pn * 2 + t2], ah[mt], bh4 + t2 * 2);
            }
        }
    }
}
#define FRAG_OFFS(l, wm, wn, aoff, boff)                                            \
    const uint32_t aoff = (uint32_t)((((wm) * 32 + ((l) & 15)) * RS + (((l) >> 4) << 3)) * 2); \
    const uint32_t boff = (uint32_t)((((wn) * 64 + ((l) & 7) + (((l) >> 4) & 1) * 8) * RS     \
                                      + (((l) >> 3) & 1) * 8) * 2)

// ================== projection GEMMs =========================================
// MODE 0: silu -> fp16 g_qh/g_kh/g_vh (+ fused q*q_decay into g_qs);
// MODE 1: sigmoid -> g_gate (fp16); MODE 2: -> C (fp32).
template <int MODE>
__global__ void __launch_bounds__(256, 2) gemm_hmma(
    const __half* __restrict__ A, const __half* __restrict__ B,
    float* __restrict__ C, int K, int Ndim, const float* __restrict__ slope) {
    extern __shared__ char smem[];
    const uint32_t sbase = smem_u32(smem);
    const int tid = threadIdx.x;
    const int l = tid & 31, wid = tid >> 5;
    const int wm = wid & 3, wn = wid >> 2;
    const int n0 = blockIdx.x * 128;
    const int m0 = blockIdx.y * 128;
    FRAG_OFFS(l, wm, wn, aoff, boff);

    float acc[2][8][4];
#pragma unroll
    for (int a = 0; a < 2; a++)
#pragma unroll
        for (int b = 0; b < 8; b++)
#pragma unroll
            for (int c = 0; c < 4; c++) acc[a][b][c] = 0.f;

    mma_pipe(sbase, tid, A + (size_t)m0 * K, B + (size_t)n0 * K, K, K, K / 32,
             aoff, boff, acc);

    const int mbase = m0 + wm * 32 + (l >> 2);
    const int dbase = wn * 64 + (l & 3) * 2;
    __half* bp0h = nullptr;
    int hh = 0, mb = 0, sidx = 0;
    float sl = 0.f;
    if (MODE == 0) {
        sidx = n0 >> 11;
        hh = (n0 & 2047) >> 7;
        mb = m0 >> 12;
        bp0h = (sidx == 0) ? g_qh : ((sidx == 1) ? g_kh : g_vh);
        sl = slope[hh];
    }
#pragma unroll
    for (int mt = 0; mt < 2; mt++)
#pragma unroll
        for (int nt = 0; nt < 8; nt++) {
            const float* cc = acc[mt][nt];
#pragma unroll
            for (int rh = 0; rh < 2; rh++) {
                const int m1 = mbase + mt * 16 + rh * 8;
                float v0 = cc[rh * 2 + 0], v1 = cc[rh * 2 + 1];
                if (MODE == 0) {
                    v0 = v0 * sigmoidf_(v0);
                    v1 = v1 * sigmoidf_(v1);
                    const int nn = m1 & 4095;
                    const int d = dbase + nt * 8;
                    const size_t base = ((size_t)(mb * NHEAD + hh) * SEQ + nn) * DH + d;
                    *(__half2*)(bp0h + base) = __floats2half2_rn(v0, v1);
                    if (sidx == 0) {
                        const float qd = expf(-sl * (float)((nn & 255) + 1));
                        *(__half2*)(g_qs + base) = __floats2half2_rn(v0 * qd, v1 * qd);
                    }
                } else if (MODE == 1) {
                    *(__half2*)(g_gate + (size_t)m1 * HID + n0 + dbase + nt * 8) =
                        __floats2half2_rn(sigmoidf_(v0), sigmoidf_(v1));
                } else {
                    *(float2*)(C + (size_t)m1 * Ndim + n0 + dbase + nt * 8) =
                        make_float2(v0, v1);
                }
            }
        }
}

// ---------- transpose k (with k_decay) and v into [z][d][t] layout -----------
__global__ void __launch_bounds__(256) transpose_kernel(const float* __restrict__ slope) {
    const int which = blockIdx.x;           // 0 = k, 1 = v
    const int z = blockIdx.y;
    const int bh = z >> 4, blk = z & 15;
    const __half* src = (which ? g_vh : g_kh) + ((size_t)bh * SEQ + blk * BLK) * DH;
    __half* dst = (which ? g_vt : g_kt) + (size_t)z * DH * BLK;
    const float s = slope[bh & 15];
    __shared__ __half tile[64][72];
    const int r = threadIdx.x >> 2;          // 0..63
    const int c16 = (threadIdx.x & 3) * 16;  // 0,16,32,48
    for (int tc = 0; tc < 4; tc++) {
        for (int dc = 0; dc < 2; dc++) {
            const int t = tc * 64 + r;
            const float kd = which ? 1.f : expf(-s * (float)(255 - t));
            __half hv[16];
            *(uint4*)hv = *(const uint4*)(src + (size_t)t * DH + dc * 64 + c16);
            *(uint4*)(hv + 8) = *(const uint4*)(src + (size_t)t * DH + dc * 64 + c16 + 8);
            if (!which) {
#pragma unroll
                for (int j = 0; j < 16; j++)
                    hv[j] = __float2half_rn(__half2float(hv[j]) * kd);
            }
#pragma unroll
            for (int j = 0; j < 16; j++) tile[r][c16 + j] = hv[j];
            __syncthreads();
            __half ob[16];
#pragma unroll
            for (int j = 0; j < 16; j++) ob[j] = tile[c16 + j][r];
            __half* op = dst + (size_t)(dc * 64 + r) * BLK + tc * 64 + c16;
            *(uint4*)op = *(uint4*)ob;
            *(uint4*)(op + 8) = *(uint4*)(ob + 8);
            __syncthreads();
        }
    }
}

// ---------- per-block KV: C[d,e] = sum_t kt[d,t] * vt[e,t]  (fp16 MMA) -------
__global__ void __launch_bounds__(256, 2) kvblk_mma() {
    extern __shared__ char smem[];
    const uint32_t sbase = smem_u32(smem);
    const int tid = threadIdx.x;
    const int l = tid & 31, wid = tid >> 5;
    const int wm = wid & 3, wn = wid >> 2;
    const int z = blockIdx.x;
    FRAG_OFFS(l, wm, wn, aoff, boff);
    float acc[2][8][4];
#pragma unroll
    for (int a = 0; a < 2; a++)
#pragma unroll
        for (int b = 0; b < 8; b++)
#pragma unroll
            for (int c = 0; c < 4; c++) acc[a][b][c] = 0.f;
    mma_pipe(sbase, tid, g_kt + (size_t)z * DH * BLK, g_vt + (size_t)z * DH * BLK,
             BLK, BLK, BLK / 32, aoff, boff, acc);
    float* Co = g_kvblk + (size_t)z * DH * DH;
    const int mbase = wm * 32 + (l >> 2);
    const int dbase = wn * 64 + (l & 3) * 2;
#pragma unroll
    for (int mt = 0; mt < 2; mt++)
#pragma unroll
        for (int nt = 0; nt < 8; nt++)
#pragma unroll
            for (int rh = 0; rh < 2; rh++) {
                const int m1 = mbase + mt * 16 + rh * 8;
                *(float2*)(Co + (size_t)m1 * DH + dbase + nt * 8) =
                    make_float2(acc[mt][nt][rh * 2], acc[mt][nt][rh * 2 + 1]);
            }
}

// ---------- exclusive scan -> transposed fp16 kvstate ------------------------
__global__ void __launch_bounds__(256) scan_kernel(const float* __restrict__ slope) {
    const int bh = blockIdx.x >> 6;
    const int f = (blockIdx.x & 63) * 256 + threadIdx.x;  // f = d*128 + e
    const int d_ = f >> 7, e_ = f & 127;
    const float decay = expf(-slope[bh & 15] * (float)BLK);
    const float* src = g_kvblk + (size_t)bh * NB * DH * DH + f;
    __half* dstT = g_kvt + (size_t)bh * NB * DH * DH + e_ * DH + d_;
    float acc = 0.f;
#pragma unroll
    for (int i = 0; i < NB; i++) {
        dstT[(size_t)i * DH * DH] = __float2half_rn(acc);
        acc = decay * acc + src[(size_t)i * DH * DH];
    }
}

// ---------- S = (Q K^T) * causal decay -> fp16, 3 quadrants per z ------------
__global__ void __launch_bounds__(256, 2) qk_mma(const float* __restrict__ slope) {
    extern __shared__ char smem[];
    const uint32_t sbase = smem_u32(smem);
    const int tid = threadIdx.x;
    const int l = tid & 31, wid = tid >> 5;
    const int wm = wid & 3, wn = wid >> 2;
    const int z = blockIdx.y;
    const int quad = blockIdx.x;           // 0:(0,0) 1:(1,0) 2:(1,1)
    const int ti = (quad + 1) >> 1, ui = quad >> 1;
    const int bh = z >> 4, blk = z & 15;
    const float s = slope[bh & 15];
    FRAG_OFFS(l, wm, wn, aoff, boff);
    float acc[2][8][4];
#pragma unroll
    for (int a = 0; a < 2; a++)
#pragma unroll
        for (int b = 0; b < 8; b++)
#pragma unroll
            for (int c = 0; c < 4; c++) acc[a][b][c] = 0.f;
    mma_pipe(sbase, tid,
             g_qh + ((size_t)bh * SEQ + blk * BLK + ti * 128) * DH,
             g_kh + ((size_t)bh * SEQ + blk * BLK + ui * 128) * DH,
             DH, DH, DH / 32, aoff, boff, acc);
    __half* So = g_Sh + (size_t)z * BLK * BLK;
    const int mbase = wm * 32 + (l >> 2);
    const int dbase = wn * 64 + (l & 3) * 2;
#pragma unroll
    for (int mt = 0; mt < 2; mt++)
#pragma unroll
        for (int nt = 0; nt < 8; nt++)
#pragma unroll
            for (int rh = 0; rh < 2; rh++) {
                const int tt = ti * 128 + mbase + mt * 16 + rh * 8;
                const int u0 = ui * 128 + dbase + nt * 8;
                float v0 = (u0 <= tt) ? acc[mt][nt][rh * 2] * expf(-s * (float)(tt - u0)) : 0.f;
                float v1 = (u0 + 1 <= tt) ? acc[mt][nt][rh * 2 + 1] * expf(-s * (float)(tt - u0 - 1)) : 0.f;
                *(__half2*)(So + (size_t)tt * BLK + u0) = __floats2half2_rn(v0, v1);
            }
}

// ---------- out = q_s @ kvstate^T + S @ v^T  (fp16 MMA, 2 halves per z) ------
__global__ void __launch_bounds__(256, 2) attnout_mma() {
    extern __shared__ char smem[];
    const uint32_t sbase = smem_u32(smem);
    const int tid = threadIdx.x;
    const int l = tid & 31, wid = tid >> 5;
    const int wm = wid & 3, wn = wid >> 2;
    const int z = blockIdx.y;
    const int thalf = blockIdx.x;
    const int bh = z >> 4, blk = z & 15;
    FRAG_OFFS(l, wm, wn, aoff, boff);
    float acc[2][8][4];
#pragma unroll
    for (int a = 0; a < 2; a++)
#pragma unroll
        for (int b = 0; b < 8; b++)
#pragma unroll
            for (int c = 0; c < 4; c++) acc[a][b][c] = 0.f;
    // phase 1: inter = (q*qd) @ kvstate   (K = d = 128)
    mma_pipe(sbase, tid,
             g_qs + ((size_t)bh * SEQ + blk * BLK + thalf * 128) * DH,
             g_kvt + (size_t)z * DH * DH,
             DH, DH, DH / 32, aoff, boff, acc);
    __syncthreads();
    // phase 2: intra = S @ v   (K = u = 128 or 256)
    const int uend = thalf ? BLK : 128;
    mma_pipe(sbase, tid,
             g_Sh + (size_t)z * BLK * BLK + (size_t)(thalf * 128) * BLK,
             g_vt + (size_t)z * DH * BLK,
             BLK, BLK, uend / 32, aoff, boff, acc);
    const int mbase = wm * 32 + (l >> 2);
    const int dbase = wn * 64 + (l & 3) * 2;
#pragma unroll
    for (int mt = 0; mt < 2; mt++)
#pragma unroll
        for (int nt = 0; nt < 8; nt++)
#pragma unroll
            for (int rh = 0; rh < 2; rh++) {
                const int m1 = mbase + mt * 16 + rh * 8;
                const int nloc = blk * BLK + thalf * 128 + m1;
                *(__half2*)(g_attn + ((size_t)bh * SEQ + nloc) * DH + dbase + nt * 8) =
                    __floats2half2_rn(acc[mt][nt][rh * 2], acc[mt][nt][rh * 2 + 1]);
            }
}

// ------------- RMSNorm + gate -> gated fp16 (ready for out-GEMM) -------------
__global__ void __launch_bounds__(256) normgate_kernel(const float* __restrict__ norm_w) {
    const int row = blockIdx.x;
    const int bi = row >> 12;
    const int nn = row & 4095;
    const int tid = threadIdx.x;
    float vals[8];
    float ss = 0.f;
#pragma unroll
    for (int j0 = 0; j0 < 8; j0++) {
        const int j = tid + j0 * 256;
        const int hh = j >> 7, dd = j & 127;
        const float v = __half2float(g_attn[((size_t)(bi * NHEAD + hh) * SEQ + nn) * DH + dd]);
        vals[j0] = v;
        ss += v * v;
    }
#pragma unroll
    for (int o = 16; o > 0; o >>= 1) ss += __shfl_xor_sync(0xffffffffu, ss, o);
    __shared__ float red[8];
    __shared__ float scale_s;
    if ((tid & 31) == 0) red[tid >> 5] = ss;
    __syncthreads();
    if (tid == 0) {
        float t = 0.f;
#pragma unroll
        for (int w = 0; w < 8; w++) t += red[w];
        scale_s = rsqrtf(t / (float)HID + 1e-6f);
    }
    __syncthreads();
    const float sc = scale_s;
#pragma unroll
    for (int j0 = 0; j0 < 8; j0++) {
        const int j = tid + j0 * 256;
        const float g = __half2float(g_gate[(size_t)row * HID + j]);
        const float v = g * vals[j0] * sc * norm_w[j];
        g_gated_h[(size_t)row * HID + j] = __float2half_rn(v);
    }
}

// --------------------------------- launch -----------------------------------
extern "C" void kernel_launch(void* const* d_in, const int* in_sizes, int n_in,
                              void* d_out, int out_size) {
    (void)in_sizes; (void)n_in; (void)out_size;
    const float* hidden = (const float*)d_in[0];
    const float* slope  = (const float*)d_in[1];
    const float* w_qkv  = (const float*)d_in[2];
    const float* w_gate = (const float*)d_in[3];
    const float* w_out  = (const float*)d_in[4];
    const float* norm_w = (const float*)d_in[5];
    float* out = (float*)d_out;

    cudaFuncSetAttribute(gemm_hmma<0>, cudaFuncAttributeMaxDynamicSharedMemorySize, SMEM_GEMM);
    cudaFuncSetAttribute(gemm_hmma<1>, cudaFuncAttributeMaxDynamicSharedMemorySize, SMEM_GEMM);
    cudaFuncSetAttribute(gemm_hmma<2>, cudaFuncAttributeMaxDynamicSharedMemorySize, SMEM_GEMM);
    cudaFuncSetAttribute(kvblk_mma,   cudaFuncAttributeMaxDynamicSharedMemorySize, SMEM_GEMM);
    cudaFuncSetAttribute(qk_mma,      cudaFuncAttributeMaxDynamicSharedMemorySize, SMEM_GEMM);
    cudaFuncSetAttribute(attnout_mma, cudaFuncAttributeMaxDynamicSharedMemorySize, SMEM_GEMM);

    __half *hid_h, *wq_h, *wg_h, *wo_h, *gd_h;
    cudaGetSymbolAddress((void**)&hid_h, g_hid_h);
    cudaGetSymbolAddress((void**)&wq_h, g_wqkv_h);
    cudaGetSymbolAddress((void**)&wg_h, g_wg_h);
    cudaGetSymbolAddress((void**)&wo_h, g_wo_h);
    cudaGetSymbolAddress((void**)&gd_h, g_gated_h);

    const bool fork = (g_sb != nullptr) && (g_e1 != nullptr) && (g_e2 != nullptr)
                      && (g_e3 != nullptr);

    // 0. fp32 -> fp16 conversions; gate/out weights on side stream (overlap
    //    with hidden/wqkv cvt + QKV GEMM on main).
    if (fork) {
        cvt_kernel<<<(HID * HID / 4 + 255) / 256, 256, 0, g_sb>>>(w_gate, wg_h, HID * HID / 4);
        cvt_kernel<<<(HID * HID / 4 + 255) / 256, 256, 0, g_sb>>>(w_out, wo_h, HID * HID / 4);
    } else {
        cvt_kernel<<<(HID * HID / 4 + 255) / 256, 256>>>(w_gate, wg_h, HID * HID / 4);
        cvt_kernel<<<(HID * HID / 4 + 255) / 256, 256>>>(w_out, wo_h, HID * HID / 4);
    }
    cvt_kernel<<<(MROWS * HID / 4 + 255) / 256, 256>>>(hidden, hid_h, MROWS * HID / 4);
    cvt_kernel<<<(QKVC * HID / 4 + 255) / 256, 256>>>(w_qkv, wq_h, QKVC * HID / 4);

    // 1. QKV projection + SiLU + fp16 scatter (+ fused q*q_decay)
    gemm_hmma<0><<<dim3(QKVC / 128, MROWS / 128), 256, SMEM_GEMM>>>(
        hid_h, wq_h, nullptr, HID, QKVC, slope);

    if (fork) {
        // SIDE: qk (needed by attnout) first, then gate GEMM (needed by normgate).
        cudaEventRecord(g_e1, 0);
        cudaStreamWaitEvent(g_sb, g_e1, 0);
        qk_mma<<<dim3(3, NZ), 256, SMEM_GEMM, g_sb>>>(slope);
        cudaEventRecord(g_e3, g_sb);
        gemm_hmma<1><<<dim3(HID / 128, MROWS / 128), 256, SMEM_GEMM, g_sb>>>(
            hid_h, wg_h, nullptr, HID, HID, slope);
        cudaEventRecord(g_e2, g_sb);
    }

    // 2. MAIN: KV-state chain (independent of qk)
    transpose_kernel<<<dim3(2, NZ), 256>>>(slope);
    kvblk_mma<<<NZ, 256, SMEM_GEMM>>>();
    scan_kernel<<<BHN * 64, 256>>>(slope);

    if (fork) {
        cudaStreamWaitEvent(0, g_e3, 0);   // attnout needs S from qk
    } else {
        qk_mma<<<dim3(3, NZ), 256, SMEM_GEMM>>>(slope);
    }
    attnout_mma<<<dim3(2, NZ), 256, SMEM_GEMM>>>();

    if (fork) {
        cudaStreamWaitEvent(0, g_e2, 0);   // normgate needs gate GEMM
    } else {
        gemm_hmma<1><<<dim3(HID / 128, MROWS / 128), 256, SMEM_GEMM>>>(
            hid_h, wg_h, nullptr, HID, HID, slope);
    }

    // 4. RMSNorm + gate -> gated fp16
    normgate_kernel<<<MROWS, 256>>>(norm_w);
    // 5. Output projection
    gemm_hmma<2><<<dim3(HID / 128, MROWS / 128), 256, SMEM_GEMM>>>(
        gd_h, wo_h, out, HID, HID, slope);
}

// round 16
// speedup vs baseline: 1.1551x; 1.0171x over previous
#include <cuda_runtime.h>
#include <cuda_fp16.h>
#include <math.h>
#include <stdint.h>

// Problem constants (fixed shapes from reference)
#define BD     2
#define SEQ    4096
#define HID    2048
#define NHEAD  16
#define DH     128
#define BLK    256
#define NB     16          // SEQ/BLK
#define MROWS  8192        // BD*SEQ
#define QKVC   6144        // 3*HID
#define COMBC  (QKVC + HID) // 8192: qkv + gate combined N
#define BHN    32          // BD*NHEAD
#define NZ     (BHN * NB)  // 512 (bh, blk) pairs

// ---------------- scratch (static device memory; no allocs allowed) ----------
__device__ __half g_attn[BHN * SEQ * DH];        // attention output (b,h,n,d) fp16
__device__ __half g_gate[MROWS * HID];           // sigmoid(x @ Wg^T) fp16
__device__ float  g_kvblk[NZ * DH * DH];         // per-block KV contributions fp32
__device__ __half g_qh[BHN * SEQ * DH];          // q fp16 (b,h,n,d)
__device__ __half g_kh[BHN * SEQ * DH];
__device__ __half g_vh[BHN * SEQ * DH];
__device__ __half g_kt[NZ * DH * BLK];           // k_decay*k transposed [z][d][t]
__device__ __half g_vt[NZ * DH * BLK];           // v transposed [z][e][u]
__device__ __half g_Sh[NZ * BLK * BLK];          // masked QK^T fp16 [z][t][u]
__device__ __half g_kvt[NZ * DH * DH];           // scanned KV state transposed [z][e][d]
// fp16 operand buffers for projection GEMMs
__device__ __half g_hid_h[MROWS * HID];
__device__ __half g_wcomb_h[COMBC * HID];        // [w_qkv ; w_gate] fp16
__device__ __half g_wo_h[HID * HID];
__device__ __half g_gated_h[MROWS * HID];

__device__ __forceinline__ float sigmoidf_(float x) { return 1.f / (1.f + expf(-x)); }

// ---- side stream + fork/join events, created at static-init time.
static cudaStream_t g_sb = nullptr;
static cudaEvent_t  g_e1 = nullptr, g_e3 = nullptr;
namespace {
struct StreamInit {
    StreamInit() {
        if (cudaStreamCreateWithFlags(&g_sb, cudaStreamNonBlocking) != cudaSuccess) { g_sb = nullptr; return; }
        if (cudaEventCreateWithFlags(&g_e1, cudaEventDisableTiming) != cudaSuccess) { g_e1 = nullptr; }
        if (cudaEventCreateWithFlags(&g_e3, cudaEventDisableTiming) != cudaSuccess) { g_e3 = nullptr; }
    }
};
StreamInit g_stream_init;
}

// =================== PTX helpers (baseline compute_103 ISA only) =============
__device__ __forceinline__ uint32_t smem_u32(const void* p) {
    uint32_t a;
    asm("{ .reg .u64 t; cvta.to.shared.u64 t, %1; cvt.u32.u64 %0, t; }" : "=r"(a) : "l"(p));
    return a;
}
__device__ __forceinline__ void cpa16(uint32_t dst, const void* src) {
    asm volatile("cp.async.cg.shared.global [%0], [%1], 16;" :: "r"(dst), "l"(src) : "memory");
}
#define CP_COMMIT() asm volatile("cp.async.commit_group;" ::: "memory")
#define CP_WAIT1()  asm volatile("cp.async.wait_group 1;" ::: "memory")

__device__ __forceinline__ void ldm4(uint32_t* r, uint32_t addr) {
    asm volatile("ldmatrix.sync.aligned.m8n8.x4.shared.b16 {%0,%1,%2,%3}, [%4];"
        : "=r"(r[0]), "=r"(r[1]), "=r"(r[2]), "=r"(r[3]) : "r"(addr));
}
__device__ __forceinline__ void mma16816h(float* c, const uint32_t* a, const uint32_t* b) {
    asm volatile("mma.sync.aligned.m16n8k16.row.col.f32.f16.f16.f32 "
        "{%0,%1,%2,%3}, {%4,%5,%6,%7}, {%8,%9}, {%0,%1,%2,%3};"
        : "+f"(c[0]), "+f"(c[1]), "+f"(c[2]), "+f"(c[3])
        : "r"(a[0]), "r"(a[1]), "r"(a[2]), "r"(a[3]), "r"(b[0]), "r"(b[1]));
}

// ---------------- fp32 -> fp16 convert, vectorized ---------------------------
__global__ void __launch_bounds__(256) cvt_kernel(const float* __restrict__ src,
                                                  __half* __restrict__ dst, int n4) {
    int i = blockIdx.x * 256 + threadIdx.x;
    if (i >= n4) return;
    float4 v = ((const float4*)src)[i];
    __half2 a = __floats2half2_rn(v.x, v.y);
    __half2 b = __floats2half2_rn(v.z, v.w);
    uint2 u;
    u.x = *(uint32_t*)&a;
    u.y = *(uint32_t*)&b;
    ((uint2*)dst)[i] = u;
}

// ============== shared fp16 MMA tile pipeline (128x128 tile, 256 thr) ========
// 3-stage cp.async pipeline, K-chunk = 32 (proven configuration).
#define RS        40              // padded smem row stride (halves)
#define TILE_BYT  (128 * RS * 2)  // 10240
#define A_OFF     0
#define B_OFF     TILE_BYT
#define STG_BYT   (2 * TILE_BYT)  // 20480
#define SMEM_GEMM (3 * STG_BYT)   // 61440

// Accumulate C[128,128] += A[128, nch*32] * B[128, nch*32]^T (fp16, K-major).
__device__ __forceinline__ void mma_pipe(uint32_t sbase, int tid,
                                         const __half* gA, const __half* gB,
                                         int ast, int bst, int nch,
                                         uint32_t aoff, uint32_t boff,
                                         float (*acc)[8][4]) {
    const int r = tid >> 1, h = tid & 1;
    const __half* ga = gA + (size_t)r * ast + h * 16;
    const __half* gb = gB + (size_t)r * bst + h * 16;
    const uint32_t sdst = (uint32_t)(r * (RS * 2) + h * 32);
    auto issue = [&](int c, int s) {
        const uint32_t st = sbase + (uint32_t)s * STG_BYT + sdst;
        cpa16(st + A_OFF,      ga + c * 32); cpa16(st + A_OFF + 16, ga + c * 32 + 8);
        cpa16(st + B_OFF,      gb + c * 32); cpa16(st + B_OFF + 16, gb + c * 32 + 8);
    };
    issue(0, 0); CP_COMMIT();
    issue(1, 1); CP_COMMIT();
    for (int i = 0; i < nch; i++) {
        const int s = i % 3;
        CP_WAIT1();
        __syncthreads();
        if (i + 2 < nch) issue(i + 2, (i + 2) % 3);
        CP_COMMIT();
        const uint32_t stage = sbase + (uint32_t)s * STG_BYT;
#pragma unroll
        for (int ks = 0; ks < 2; ks++) {
            uint32_t ah[2][4];
            ldm4(ah[0], stage + A_OFF + aoff + ks * 32);
            ldm4(ah[1], stage + A_OFF + aoff + 1280 + ks * 32);
#pragma unroll
            for (int pn = 0; pn < 4; pn++) {
                uint32_t bh4[4];
                ldm4(bh4, stage + B_OFF + boff + pn * 1280 + ks * 32);
#pragma unroll
                for (int mt = 0; mt < 2; mt++)
#pragma unroll
                    for (int t2 = 0; t2 < 2; t2++)
                        mma16816h(acc[mt][pn * 2 + t2], ah[mt], bh4 + t2 * 2);
            }
        }
    }
}
#define FRAG_OFFS(l, wm, wn, aoff, boff)                                            \
    const uint32_t aoff = (uint32_t)((((wm) * 32 + ((l) & 15)) * RS + (((l) >> 4) << 3)) * 2); \
    const uint32_t boff = (uint32_t)((((wn) * 64 + ((l) & 7) + (((l) >> 4) & 1) * 8) * RS     \
                                      + (((l) >> 3) & 1) * 8) * 2)

// ================== projection GEMMs =========================================
// MODE 0 (combined): sidx 0-2 -> silu -> fp16 g_qh/g_kh/g_vh; sidx 3 -> sigmoid
// -> g_gate (fp16). MODE 2: -> C (fp32).
template <int MODE>
__global__ void __launch_bounds__(256, 2) gemm_hmma(
    const __half* __restrict__ A, const __half* __restrict__ B,
    float* __restrict__ C, int K, int Ndim) {
    extern __shared__ char smem[];
    const uint32_t sbase = smem_u32(smem);
    const int tid = threadIdx.x;
    const int l = tid & 31, wid = tid >> 5;
    const int wm = wid & 3, wn = wid >> 2;
    const int n0 = blockIdx.x * 128;
    const int m0 = blockIdx.y * 128;
    FRAG_OFFS(l, wm, wn, aoff, boff);

    float acc[2][8][4];
#pragma unroll
    for (int a = 0; a < 2; a++)
#pragma unroll
        for (int b = 0; b < 8; b++)
#pragma unroll
            for (int c = 0; c < 4; c++) acc[a][b][c] = 0.f;

    mma_pipe(sbase, tid, A + (size_t)m0 * K, B + (size_t)n0 * K, K, K, K / 32,
             aoff, boff, acc);

    const int mbase = m0 + wm * 32 + (l >> 2);
    const int dbase = wn * 64 + (l & 3) * 2;
    __half* bp0h = nullptr;
    int hh = 0, mb = 0, sidx = 0;
    if (MODE == 0) {
        sidx = n0 >> 11;                  // 0:q 1:k 2:v 3:gate
        hh = (n0 & 2047) >> 7;
        mb = m0 >> 12;
        bp0h = (sidx == 0) ? g_qh : ((sidx == 1) ? g_kh : g_vh);
    }
#pragma unroll
    for (int mt = 0; mt < 2; mt++)
#pragma unroll
        for (int nt = 0; nt < 8; nt++) {
            const float* cc = acc[mt][nt];
#pragma unroll
            for (int rh = 0; rh < 2; rh++) {
                const int m1 = mbase + mt * 16 + rh * 8;
                float v0 = cc[rh * 2 + 0], v1 = cc[rh * 2 + 1];
                if (MODE == 0) {
                    if (sidx < 3) {
                        v0 = v0 * sigmoidf_(v0);
                        v1 = v1 * sigmoidf_(v1);
                        const int nn = m1 & 4095;
                        const int d = dbase + nt * 8;
                        *(__half2*)(bp0h + ((size_t)(mb * NHEAD + hh) * SEQ + nn) * DH + d) =
                            __floats2half2_rn(v0, v1);
                    } else {
                        *(__half2*)(g_gate + (size_t)m1 * HID + (n0 - QKVC) + dbase + nt * 8) =
                            __floats2half2_rn(sigmoidf_(v0), sigmoidf_(v1));
                    }
                } else {
                    *(float2*)(C + (size_t)m1 * Ndim + n0 + dbase + nt * 8) =
                        make_float2(v0, v1);
                }
            }
        }
}

// ---------- transpose k (with k_decay) and v into [z][d][t] layout -----------
__global__ void __launch_bounds__(256) transpose_kernel(const float* __restrict__ slope) {
    const int which = blockIdx.x;           // 0 = k, 1 = v
    const int z = blockIdx.y;
    const int bh = z >> 4, blk = z & 15;
    const __half* src = (which ? g_vh : g_kh) + ((size_t)bh * SEQ + blk * BLK) * DH;
    __half* dst = (which ? g_vt : g_kt) + (size_t)z * DH * BLK;
    const float s = slope[bh & 15];
    __shared__ __half tile[64][72];
    const int r = threadIdx.x >> 2;          // 0..63
    const int c16 = (threadIdx.x & 3) * 16;  // 0,16,32,48
    for (int tc = 0; tc < 4; tc++) {
        for (int dc = 0; dc < 2; dc++) {
            const int t = tc * 64 + r;
            const float kd = which ? 1.f : expf(-s * (float)(255 - t));
            __half hv[16];
            *(uint4*)hv = *(const uint4*)(src + (size_t)t * DH + dc * 64 + c16);
            *(uint4*)(hv + 8) = *(const uint4*)(src + (size_t)t * DH + dc * 64 + c16 + 8);
            if (!which) {
#pragma unroll
                for (int j = 0; j < 16; j++)
                    hv[j] = __float2half_rn(__half2float(hv[j]) * kd);
            }
#pragma unroll
            for (int j = 0; j < 16; j++) tile[r][c16 + j] = hv[j];
            __syncthreads();
            __half ob[16];
#pragma unroll
            for (int j = 0; j < 16; j++) ob[j] = tile[c16 + j][r];
            __half* op = dst + (size_t)(dc * 64 + r) * BLK + tc * 64 + c16;
            *(uint4*)op = *(uint4*)ob;
            *(uint4*)(op + 8) = *(uint4*)(ob + 8);
            __syncthreads();
        }
    }
}

// ---------- per-block KV: C[d,e] = sum_t kt[d,t] * vt[e,t]  (fp16 MMA) -------
__global__ void __launch_bounds__(256, 2) kvblk_mma() {
    extern __shared__ char smem[];
    const uint32_t sbase = smem_u32(smem);
    const int tid = threadIdx.x;
    const int l = tid & 31, wid = tid >> 5;
    const int wm = wid & 3, wn = wid >> 2;
    const int z = blockIdx.x;
    FRAG_OFFS(l, wm, wn, aoff, boff);
    float acc[2][8][4];
#pragma unroll
    for (int a = 0; a < 2; a++)
#pragma unroll
        for (int b = 0; b < 8; b++)
#pragma unroll
            for (int c = 0; c < 4; c++) acc[a][b][c] = 0.f;
    mma_pipe(sbase, tid, g_kt + (size_t)z * DH * BLK, g_vt + (size_t)z * DH * BLK,
             BLK, BLK, BLK / 32, aoff, boff, acc);
    float* Co = g_kvblk + (size_t)z * DH * DH;
    const int mbase = wm * 32 + (l >> 2);
    const int dbase = wn * 64 + (l & 3) * 2;
#pragma unroll
    for (int mt = 0; mt < 2; mt++)
#pragma unroll
        for (int nt = 0; nt < 8; nt++)
#pragma unroll
            for (int rh = 0; rh < 2; rh++) {
                const int m1 = mbase + mt * 16 + rh * 8;
                *(float2*)(Co + (size_t)m1 * DH + dbase + nt * 8) =
                    make_float2(acc[mt][nt][rh * 2], acc[mt][nt][rh * 2 + 1]);
            }
}

// ---------- exclusive scan -> transposed fp16 kvstate ------------------------
__global__ void __launch_bounds__(256) scan_kernel(const float* __restrict__ slope) {
    const int bh = blockIdx.x >> 6;
    const int f = (blockIdx.x & 63) * 256 + threadIdx.x;  // f = d*128 + e
    const int d_ = f >> 7, e_ = f & 127;
    const float decay = expf(-slope[bh & 15] * (float)BLK);
    const float* src = g_kvblk + (size_t)bh * NB * DH * DH + f;
    __half* dstT = g_kvt + (size_t)bh * NB * DH * DH + e_ * DH + d_;
    float acc = 0.f;
#pragma unroll
    for (int i = 0; i < NB; i++) {
        dstT[(size_t)i * DH * DH] = __float2half_rn(acc);
        acc = decay * acc + src[(size_t)i * DH * DH];
    }
}

// ---------- S = (Q K^T) * causal decay -> fp16, 3 quadrants per z ------------
__global__ void __launch_bounds__(256, 2) qk_mma(const float* __restrict__ slope) {
    extern __shared__ char smem[];
    const uint32_t sbase = smem_u32(smem);
    const int tid = threadIdx.x;
    const int l = tid & 31, wid = tid >> 5;
    const int wm = wid & 3, wn = wid >> 2;
    const int z = blockIdx.y;
    const int quad = blockIdx.x;           // 0:(0,0) 1:(1,0) 2:(1,1)
    const int ti = (quad + 1) >> 1, ui = quad >> 1;
    const int bh = z >> 4, blk = z & 15;
    const float s = slope[bh & 15];
    FRAG_OFFS(l, wm, wn, aoff, boff);
    float acc[2][8][4];
#pragma unroll
    for (int a = 0; a < 2; a++)
#pragma unroll
        for (int b = 0; b < 8; b++)
#pragma unroll
            for (int c = 0; c < 4; c++) acc[a][b][c] = 0.f;
    mma_pipe(sbase, tid,
             g_qh + ((size_t)bh * SEQ + blk * BLK + ti * 128) * DH,
             g_kh + ((size_t)bh * SEQ + blk * BLK + ui * 128) * DH,
             DH, DH, DH / 32, aoff, boff, acc);
    __half* So = g_Sh + (size_t)z * BLK * BLK;
    const int mbase = wm * 32 + (l >> 2);
    const int dbase = wn * 64 + (l & 3) * 2;
#pragma unroll
    for (int mt = 0; mt < 2; mt++)
#pragma unroll
        for (int nt = 0; nt < 8; nt++)
#pragma unroll
            for (int rh = 0; rh < 2; rh++) {
                const int tt = ti * 128 + mbase + mt * 16 + rh * 8;
                const int u0 = ui * 128 + dbase + nt * 8;
                float v0 = (u0 <= tt) ? acc[mt][nt][rh * 2] * expf(-s * (float)(tt - u0)) : 0.f;
                float v1 = (u0 + 1 <= tt) ? acc[mt][nt][rh * 2 + 1] * expf(-s * (float)(tt - u0 - 1)) : 0.f;
                *(__half2*)(So + (size_t)tt * BLK + u0) = __floats2half2_rn(v0, v1);
            }
}

// ---------- out = qd*(q @ kvstate^T) + S @ v^T  (fp16 MMA, 2 halves/z) -------
// q_decay folded as per-row fp32 scale on the phase-1 accumulator.
__global__ void __launch_bounds__(256, 2) attnout_mma(const float* __restrict__ slope) {
    extern __shared__ char smem[];
    const uint32_t sbase = smem_u32(smem);
    const int tid = threadIdx.x;
    const int l = tid & 31, wid = tid >> 5;
    const int wm = wid & 3, wn = wid >> 2;
    const int z = blockIdx.y;
    const int thalf = blockIdx.x;
    const int bh = z >> 4, blk = z & 15;
    const float s = slope[bh & 15];
    FRAG_OFFS(l, wm, wn, aoff, boff);
    float acc[2][8][4];
#pragma unroll
    for (int a = 0; a < 2; a++)
#pragma unroll
        for (int b = 0; b < 8; b++)
#pragma unroll
            for (int c = 0; c < 4; c++) acc[a][b][c] = 0.f;
    // phase 1: q @ kvstate   (K = d = 128)
    mma_pipe(sbase, tid,
             g_qh + ((size_t)bh * SEQ + blk * BLK + thalf * 128) * DH,
             g_kvt + (size_t)z * DH * DH,
             DH, DH, DH / 32, aoff, boff, acc);
    // scale inter term by q_decay (per accumulator row, exact fp32)
    const int mbase = wm * 32 + (l >> 2);
#pragma unroll
    for (int mt = 0; mt < 2; mt++)
#pragma unroll
        for (int rh = 0; rh < 2; rh++) {
            const float qd = expf(-s * (float)(thalf * 128 + mbase + mt * 16 + rh * 8 + 1));
#pragma unroll
            for (int nt = 0; nt < 8; nt++) {
                acc[mt][nt][rh * 2 + 0] *= qd;
                acc[mt][nt][rh * 2 + 1] *= qd;
            }
        }
    __syncthreads();
    // phase 2: intra = S @ v   (K = u = 128 or 256)
    const int uend = thalf ? BLK : 128;
    mma_pipe(sbase, tid,
             g_Sh + (size_t)z * BLK * BLK + (size_t)(thalf * 128) * BLK,
             g_vt + (size_t)z * DH * BLK,
             BLK, BLK, uend / 32, aoff, boff, acc);
    const int dbase = wn * 64 + (l & 3) * 2;
#pragma unroll
    for (int mt = 0; mt < 2; mt++)
#pragma unroll
        for (int nt = 0; nt < 8; nt++)
#pragma unroll
            for (int rh = 0; rh < 2; rh++) {
                const int m1 = mbase + mt * 16 + rh * 8;
                const int nloc = blk * BLK + thalf * 128 + m1;
                *(__half2*)(g_attn + ((size_t)bh * SEQ + nloc) * DH + dbase + nt * 8) =
                    __floats2half2_rn(acc[mt][nt][rh * 2], acc[mt][nt][rh * 2 + 1]);
            }
}

// ------------- RMSNorm + gate -> gated fp16 (ready for out-GEMM) -------------
__global__ void __launch_bounds__(256) normgate_kernel(const float* __restrict__ norm_w) {
    const int row = blockIdx.x;
    const int bi = row >> 12;
    const int nn = row & 4095;
    const int tid = threadIdx.x;
    float vals[8];
    float ss = 0.f;
#pragma unroll
    for (int j0 = 0; j0 < 8; j0++) {
        const int j = tid + j0 * 256;
        const int hh = j >> 7, dd = j & 127;
        const float v = __half2float(g_attn[((size_t)(bi * NHEAD + hh) * SEQ + nn) * DH + dd]);
        vals[j0] = v;
        ss += v * v;
    }
#pragma unroll
    for (int o = 16; o > 0; o >>= 1) ss += __shfl_xor_sync(0xffffffffu, ss, o);
    __shared__ float red[8];
    __shared__ float scale_s;
    if ((tid & 31) == 0) red[tid >> 5] = ss;
    __syncthreads();
    if (tid == 0) {
        float t = 0.f;
#pragma unroll
        for (int w = 0; w < 8; w++) t += red[w];
        scale_s = rsqrtf(t / (float)HID + 1e-6f);
    }
    __syncthreads();
    const float sc = scale_s;
#pragma unroll
    for (int j0 = 0; j0 < 8; j0++) {
        const int j = tid + j0 * 256;
        const float g = __half2float(g_gate[(size_t)row * HID + j]);
        const float v = g * vals[j0] * sc * norm_w[j];
        g_gated_h[(size_t)row * HID + j] = __float2half_rn(v);
    }
}

// --------------------------------- launch -----------------------------------
extern "C" void kernel_launch(void* const* d_in, const int* in_sizes, int n_in,
                              void* d_out, int out_size) {
    (void)in_sizes; (void)n_in; (void)out_size;
    const float* hidden = (const float*)d_in[0];
    const float* slope  = (const float*)d_in[1];
    const float* w_qkv  = (const float*)d_in[2];
    const float* w_gate = (const float*)d_in[3];
    const float* w_out  = (const float*)d_in[4];
    const float* norm_w = (const float*)d_in[5];
    float* out = (float*)d_out;

    cudaFuncSetAttribute(gemm_hmma<0>, cudaFuncAttributeMaxDynamicSharedMemorySize, SMEM_GEMM);
    cudaFuncSetAttribute(gemm_hmma<2>, cudaFuncAttributeMaxDynamicSharedMemorySize, SMEM_GEMM);
    cudaFuncSetAttribute(kvblk_mma,   cudaFuncAttributeMaxDynamicSharedMemorySize, SMEM_GEMM);
    cudaFuncSetAttribute(qk_mma,      cudaFuncAttributeMaxDynamicSharedMemorySize, SMEM_GEMM);
    cudaFuncSetAttribute(attnout_mma, cudaFuncAttributeMaxDynamicSharedMemorySize, SMEM_GEMM);

    __half *hid_h, *wc_h, *wo_h, *gd_h;
    cudaGetSymbolAddress((void**)&hid_h, g_hid_h);
    cudaGetSymbolAddress((void**)&wc_h, g_wcomb_h);
    cudaGetSymbolAddress((void**)&wo_h, g_wo_h);
    cudaGetSymbolAddress((void**)&gd_h, g_gated_h);

    const bool fork = (g_sb != nullptr) && (g_e1 != nullptr) && (g_e3 != nullptr);

    // 0. fp32 -> fp16 conversions. w_out on side stream; combined weights
    //    (qkv + gate) and hidden on main (the big GEMM reads them).
    if (fork) {
        cvt_kernel<<<(HID * HID / 4 + 255) / 256, 256, 0, g_sb>>>(w_out, wo_h, HID * HID / 4);
    } else {
        cvt_kernel<<<(HID * HID / 4 + 255) / 256, 256>>>(w_out, wo_h, HID * HID / 4);
    }
    cvt_kernel<<<(MROWS * HID / 4 + 255) / 256, 256>>>(hidden, hid_h, MROWS * HID / 4);
    cvt_kernel<<<(QKVC * HID / 4 + 255) / 256, 256>>>(w_qkv, wc_h, QKVC * HID / 4);
    cvt_kernel<<<(HID * HID / 4 + 255) / 256, 256>>>(w_gate, wc_h + (size_t)QKVC * HID, HID * HID / 4);

    // 1. Combined QKV+gate projection (one GEMM, N = 8192)
    gemm_hmma<0><<<dim3(COMBC / 128, MROWS / 128), 256, SMEM_GEMM>>>(
        hid_h, wc_h, nullptr, HID, COMBC);

    if (fork) {
        // SIDE: qk (small) overlapped with the KV-state chain on main.
        cudaEventRecord(g_e1, 0);
        cudaStreamWaitEvent(g_sb, g_e1, 0);
        qk_mma<<<dim3(3, NZ), 256, SMEM_GEMM, g_sb>>>(slope);
        cudaEventRecord(g_e3, g_sb);
    }

    // 2. MAIN: KV-state chain (independent of qk)
    transpose_kernel<<<dim3(2, NZ), 256>>>(slope);
    kvblk_mma<<<NZ, 256, SMEM_GEMM>>>();
    scan_kernel<<<BHN * 64, 256>>>(slope);

    if (fork) {
        cudaStreamWaitEvent(0, g_e3, 0);   // attnout needs S from qk
    } else {
        qk_mma<<<dim3(3, NZ), 256, SMEM_GEMM>>>(slope);
    }
    attnout_mma<<<dim3(2, NZ), 256, SMEM_GEMM>>>(slope);

    // 4. RMSNorm + gate -> gated fp16
    normgate_kernel<<<MROWS, 256>>>(norm_w);
    // 5. Output projection
    gemm_hmma<2><<<dim3(HID / 128, MROWS / 128), 256, SMEM_GEMM>>>(
        gd_h, wo_h, out, HID, HID);
}